// round 8
// baseline (speedup 1.0000x reference)
#include <cuda_runtime.h>
#include <cuda_fp16.h>
#include <cstdint>
#include <math.h>

#define BB 4
#define SS 4096
#define DD 1024
#define HH 64
#define NROW (BB*SS)

// Q scale: 1/8 softmax scale * log2(e) for ex2-based exp
#define QSC 0.18033688011112042f

// ---------------- scratch (__device__ globals; allocation-free rule) -------
__device__ uint32_t g_Xh[NROW*512];                     // [row][d-pair] f16x2
__device__ uint32_t g_Qh[NROW*32];                      // [row][d-pair] f16x2
__device__ uint32_t g_Kh[NROW*32], g_Kl[NROW*32];       // [row][d-pair]
__device__ uint32_t g_Vth[BB*64*2048], g_Vtl[BB*64*2048]; // [b][h][seq-pair]
__device__ uint32_t g_Wth[192*512], g_Wtl[192*512];     // [n(=3*64)][d-pair]
__device__ float    g_O[2][NROW*64];                    // split-k partial O
__device__ float    g_L[2][NROW];                       // split-k partial rowsum

// ---------------- helpers --------------------------------------------------
__device__ __forceinline__ uint32_t smem_u32(const void* p){
    uint32_t a;
    asm("{ .reg .u64 t; cvta.to.shared.u64 t, %1; cvt.u32.u64 %0, t; }"
        : "=r"(a) : "l"(p));
    return a;
}
__device__ __forceinline__ void mma16816(float* d, const uint32_t* a,
                                         const uint32_t* b){
    asm volatile(
        "mma.sync.aligned.m16n8k16.row.col.f32.f16.f16.f32 "
        "{%0,%1,%2,%3}, {%4,%5,%6,%7}, {%8,%9}, {%0,%1,%2,%3};"
        : "+f"(d[0]), "+f"(d[1]), "+f"(d[2]), "+f"(d[3])
        : "r"(a[0]), "r"(a[1]), "r"(a[2]), "r"(a[3]), "r"(b[0]), "r"(b[1]));
}
__device__ __forceinline__ void ldsm4(uint32_t* r, uint32_t addr){
    asm volatile("ldmatrix.sync.aligned.m8n8.x4.shared.b16 {%0,%1,%2,%3}, [%4];"
        : "=r"(r[0]), "=r"(r[1]), "=r"(r[2]), "=r"(r[3]) : "r"(addr));
}
__device__ __forceinline__ void cpasync16(uint32_t dst, const void* src){
    asm volatile("cp.async.cg.shared.global [%0], [%1], 16;"
                 :: "r"(dst), "l"(src));
}
#define CP_COMMIT() asm volatile("cp.async.commit_group;" ::: "memory")
#define CP_WAIT1()  asm volatile("cp.async.wait_group 1;" ::: "memory")
#define CP_WAIT0()  asm volatile("cp.async.wait_group 0;" ::: "memory")

__device__ __forceinline__ float ex2(float x){
    float r; asm("ex2.approx.f32 %0, %1;" : "=f"(r) : "f"(x)); return r;
}
// fp16x2 pack: f0 -> low half, f1 -> high half
__device__ __forceinline__ uint32_t pack2h(float f0, float f1){
    uint32_t r;
    asm("cvt.rn.f16x2.f32 %0, %1, %2;" : "=r"(r) : "f"(f1), "f"(f0));
    return r;
}
// split-fp16: (f0,f1) -> hi f16x2 + lo residual f16x2
__device__ __forceinline__ void split2h(float f0, float f1,
                                        uint32_t& hv, uint32_t& lv){
    hv = pack2h(f0, f1);
    __half2 h = *reinterpret_cast<__half2*>(&hv);
    float h0 = __low2float(h), h1 = __high2float(h);
    lv = pack2h(f0 - h0, f1 - h1);
}
// swizzled byte offset inside a [row][128B] tile (conflict-free ldmatrix)
__device__ __forceinline__ uint32_t swz(int r, int bytecol){
    return (uint32_t)(r*128 + (bytecol ^ ((r & 7) << 4)));
}

// ---------------------------------------------------------------------------
// Kernel 0a: convert X -> fp16 pairs.  Kernel 0b: transpose+split W.
// ---------------------------------------------------------------------------
__global__ __launch_bounds__(256) void prep_x(const float* __restrict__ X){
    int idx = blockIdx.x*256 + threadIdx.x;        // 0 .. NROW*512-1
    float2 x = ((const float2*)X)[idx];
    g_Xh[idx] = pack2h(x.x, x.y);
}
__global__ __launch_bounds__(256) void prep_w(
    const float* __restrict__ Wq, const float* __restrict__ Wk,
    const float* __restrict__ Wv)
{
    int idx = blockIdx.x*256 + threadIdx.x;
    if (idx >= 192*512) return;
    int n = idx >> 9, dp = idx & 511;
    const float* W = (n < 64) ? Wq : (n < 128) ? Wk : Wv;
    int h = n & 63, d = dp*2;
    uint32_t hv, lv;
    split2h(W[d*64 + h], W[(d+1)*64 + h], hv, lv);
    g_Wth[idx] = hv;  g_Wtl[idx] = lv;
}

// ---------------------------------------------------------------------------
// Kernel 1: QKV via mma.sync fp16 2-term (A=X hi, B=W hi+lo).
// 128 CTAs x 256 thr.  CTA: 128 rows x 192 cols.  K chunked by 64,
// cp.async double-buffered: per buffer XH 16KB @0, WH 24KB @16384,
// WL 24KB @40960 -> 64KB; 2 buffers = 128KB dynamic.
// ---------------------------------------------------------------------------
extern __shared__ char dsm[];

__global__ __launch_bounds__(256) void qkv_mma()
{
    uint32_t sb = smem_u32(dsm);
    const int tid = threadIdx.x, w = tid >> 5, lane = tid & 31;
    const int gid = lane >> 2, tig = lane & 3;
    const int row0 = blockIdx.x * 128;
    const int mrow = w * 16;

    const int aR   = mrow + (lane & 7) + ((lane >> 3) & 1) * 8;
    const uint32_t aOff = (uint32_t)aR * 128;
    const int aSeg = (lane >> 4) ? 16 : 0;
    const uint32_t aX = (uint32_t)((lane & 7) << 4);
    const uint32_t bOff = (uint32_t)((lane & 7) * 128);
    const int bSeg = (lane & 8) ? 16 : 0;
    const uint32_t bX = (uint32_t)((lane & 7) << 4);
    const int ntHi = (lane >> 4) & 1;

    float acc[24][4];
    #pragma unroll
    for (int nt = 0; nt < 24; ++nt)
        #pragma unroll
        for (int j = 0; j < 4; ++j) acc[nt][j] = 0.f;

    #define QSTAGE(buf, kc) do {                                              \
        uint32_t _b = sb + (uint32_t)(buf)*65536;                             \
        _Pragma("unroll")                                                     \
        for (int _i = 0; _i < 4; ++_i) {                                      \
            int _idx = tid + 256*_i;               /* 1024: X 16B units */    \
            int _r = _idx >> 3, _c4 = _idx & 7;                               \
            uint32_t _o = swz(_r, _c4*16);                                    \
            cpasync16(_b + _o, g_Xh + (size_t)(row0+_r)*512 + (kc)*32 + _c4*4);\
        }                                                                     \
        _Pragma("unroll")                                                     \
        for (int _i = 0; _i < 6; ++_i) {                                      \
            int _idx = tid + 256*_i;               /* 1536: W 16B units */    \
            int _r = _idx >> 3, _c4 = _idx & 7;                               \
            uint32_t _o = swz(_r, _c4*16);                                    \
            cpasync16(_b + 16384 + _o, g_Wth + (size_t)_r*512 + (kc)*32 + _c4*4);\
            cpasync16(_b + 40960 + _o, g_Wtl + (size_t)_r*512 + (kc)*32 + _c4*4);\
        }                                                                     \
        CP_COMMIT();                                                          \
    } while (0)

    QSTAGE(0, 0);

    for (int kc = 0; kc < 16; ++kc) {
        const bool more = (kc + 1 < 16);
        if (more) QSTAGE((kc+1) & 1, kc+1);
        if (more) CP_WAIT1(); else CP_WAIT0();
        __syncthreads();
        const uint32_t st = sb + (uint32_t)((kc & 1) * 65536);

        #pragma unroll
        for (int ks = 0; ks < 4; ++ks) {
            uint32_t ah[4];
            ldsm4(ah, st + aOff + (uint32_t)((ks*32 + aSeg) ^ aX));
            uint32_t kk = bOff + (uint32_t)((ks*32 + bSeg) ^ bX);
            #pragma unroll
            for (int p = 0; p < 12; ++p) {
                uint32_t bh4[4], bl4[4];
                uint32_t ta = st + 16384 + (uint32_t)((2*p + ntHi)*1024) + kk;
                ldsm4(bh4, ta);
                ldsm4(bl4, ta + 24576);
                mma16816(acc[2*p],   ah, bh4);
                mma16816(acc[2*p],   ah, bl4);
                mma16816(acc[2*p+1], ah, bh4+2);
                mma16816(acc[2*p+1], ah, bl4+2);
            }
        }
        __syncthreads();
    }
    #undef QSTAGE

    // epilogue: Q (x QSC, hi only) and K (split) row-major
    const int r0g = row0 + mrow + gid, r1g = r0g + 8;
    #pragma unroll
    for (int nt = 0; nt < 8; ++nt) {
        g_Qh[r0g*32 + nt*4 + tig] = pack2h(acc[nt][0]*QSC, acc[nt][1]*QSC);
        g_Qh[r1g*32 + nt*4 + tig] = pack2h(acc[nt][2]*QSC, acc[nt][3]*QSC);
    }
    #pragma unroll
    for (int nt = 8; nt < 16; ++nt) {
        uint32_t hv, lv;
        int c = (nt - 8)*4 + tig;
        split2h(acc[nt][0], acc[nt][1], hv, lv);
        g_Kh[r0g*32 + c] = hv;  g_Kl[r0g*32 + c] = lv;
        split2h(acc[nt][2], acc[nt][3], hv, lv);
        g_Kh[r1g*32 + c] = hv;  g_Kl[r1g*32 + c] = lv;
    }
    // V: transpose through smem, split-write [b][h][seq-pair]
    float* Vt = (float*)dsm;                       // 64*128*4 = 32KB
    #pragma unroll
    for (int nt = 16; nt < 24; ++nt) {
        int h0 = (nt - 16)*8 + tig*2;
        Vt[h0*128 + mrow + gid]         = acc[nt][0];
        Vt[(h0+1)*128 + mrow + gid]     = acc[nt][1];
        Vt[h0*128 + mrow + gid + 8]     = acc[nt][2];
        Vt[(h0+1)*128 + mrow + gid + 8] = acc[nt][3];
    }
    __syncthreads();
    const int bb = row0 >> 12, sloc = row0 & 4095;
    #pragma unroll
    for (int i = 0; i < 16; ++i) {
        int idx = tid + 256*i;
        int h = idx >> 6, sp = idx & 63;
        uint32_t hv, lv;
        split2h(Vt[h*128 + 2*sp], Vt[h*128 + 2*sp + 1], hv, lv);
        size_t o = (size_t)(bb*64 + h)*2048 + (sloc >> 1) + sp;
        g_Vth[o] = hv;  g_Vtl[o] = lv;
    }
}

// ---------------------------------------------------------------------------
// Kernel 2: causal attention, fp16 2-term (A hi-only), no-max softmax.
// grid (64, 4): qi = 31 - (bx>>1) longest-first, split s = bx&1; 256 CTAs.
// cp.async double-buffered K/V staging (2 x 32KB dynamic smem).
// ---------------------------------------------------------------------------
__global__ __launch_bounds__(256) void attn_mma()
{
    uint32_t sb = smem_u32(dsm);
    const int tid = threadIdx.x, w = tid >> 5, lane = tid & 31;
    const int gid = lane >> 2, tig = lane & 3;
    const int qq = 31 - ((int)blockIdx.x >> 1);
    const int s  = blockIdx.x & 1;
    const int b  = blockIdx.y;
    const int q0 = qq * 128;
    const int n  = qq + 1;                         // k-tiles: kt = s + 2t

    const uint32_t bOff = (uint32_t)((lane & 7) * 128);
    const int bSeg = (lane & 8) ? 16 : 0;
    const uint32_t bX = (uint32_t)((lane & 7) << 4);
    const int ntHi = (lane >> 4) & 1;

    const uint32_t* KH = g_Kh + (size_t)(b*SS)*32;
    const uint32_t* KL = g_Kl + (size_t)(b*SS)*32;
    const uint32_t* VH = g_Vth + (size_t)(b*64)*2048;
    const uint32_t* VL = g_Vtl + (size_t)(b*64)*2048;

    // Q fragments (hi only, registers)
    const int r0g = b*SS + q0 + w*16 + gid, r1g = r0g + 8;
    uint32_t qf[4][4];
    #pragma unroll
    for (int ks = 0; ks < 4; ++ks) {
        qf[ks][0] = g_Qh[r0g*32 + ks*8 + tig];
        qf[ks][1] = g_Qh[r1g*32 + ks*8 + tig];
        qf[ks][2] = g_Qh[r0g*32 + ks*8 + 4 + tig];
        qf[ks][3] = g_Qh[r1g*32 + ks*8 + 4 + tig];
    }

    float oc[8][4];
    #pragma unroll
    for (int nt = 0; nt < 8; ++nt)
        #pragma unroll
        for (int c = 0; c < 4; ++c) oc[nt][c] = 0.f;
    float ls0 = 0.f, ls1 = 0.f;
    const int qg0 = q0 + w*16 + gid, qg1 = qg0 + 8;

    #define STAGE(buf, k0) do {                                               \
        uint32_t _b = sb + (uint32_t)(buf)*32768;                             \
        _Pragma("unroll")                                                     \
        for (int _i = 0; _i < 2; ++_i) {                                      \
            int _idx = tid + 256*_i;                                          \
            int _r = _idx >> 3, _c4 = _idx & 7;                               \
            uint32_t _o = swz(_r, _c4*16);                                    \
            cpasync16(_b + _o,         KH + (size_t)((k0)+_r)*32 + _c4*4);    \
            cpasync16(_b + 8192 + _o,  KL + (size_t)((k0)+_r)*32 + _c4*4);    \
            cpasync16(_b + 16384 + _o, VH + (size_t)_r*2048 + ((k0)>>1) + _c4*4);\
            cpasync16(_b + 24576 + _o, VL + (size_t)_r*2048 + ((k0)>>1) + _c4*4);\
        }                                                                     \
        CP_COMMIT();                                                          \
    } while (0)

    STAGE(0, s*64);

    for (int t = 0; t < n; ++t) {
        const int k0 = (s + 2*t) * 64;
        const bool more = (t + 1 < n);
        if (more) STAGE((t+1) & 1, (s + 2*(t+1))*64);
        if (more) CP_WAIT1(); else CP_WAIT0();
        __syncthreads();
        const uint32_t st = sb + (uint32_t)((t & 1) * 32768);

        // scores = Q_hi . (K_hi + K_lo)
        float sc[8][4];
        #pragma unroll
        for (int nt = 0; nt < 8; ++nt)
            #pragma unroll
            for (int c = 0; c < 4; ++c) sc[nt][c] = 0.f;
        #pragma unroll
        for (int ks = 0; ks < 4; ++ks) {
            uint32_t kk = bOff + (uint32_t)((ks*32 + bSeg) ^ bX);
            #pragma unroll
            for (int p = 0; p < 4; ++p) {
                uint32_t bh4[4], bl4[4];
                uint32_t ta = st + (uint32_t)((2*p + ntHi)*1024) + kk;
                ldsm4(bh4, ta);
                ldsm4(bl4, ta + 8192);
                mma16816(sc[2*p],   qf[ks], bh4);
                mma16816(sc[2*p],   qf[ks], bl4);
                mma16816(sc[2*p+1], qf[ks], bh4+2);
                mma16816(sc[2*p+1], qf[ks], bl4+2);
            }
        }

        // mask + exp2; P -> fp16 A-fragments (one cvt per pair)
        uint32_t ph[16];
        #pragma unroll
        for (int nt = 0; nt < 8; ++nt) {
            int kg = k0 + nt*8 + tig*2;
            float p0 = (kg     <= qg0) ? ex2(sc[nt][0]) : 0.f;
            float p1 = (kg + 1 <= qg0) ? ex2(sc[nt][1]) : 0.f;
            float p2 = (kg     <= qg1) ? ex2(sc[nt][2]) : 0.f;
            float p3 = (kg + 1 <= qg1) ? ex2(sc[nt][3]) : 0.f;
            ls0 += p0 + p1;  ls1 += p2 + p3;
            ph[nt*2]     = pack2h(p0, p1);
            ph[nt*2 + 1] = pack2h(p2, p3);
        }

        // O += P_hi . (V_hi + V_lo)
        #pragma unroll
        for (int kc = 0; kc < 4; ++kc) {
            uint32_t kk = bOff + (uint32_t)((kc*32 + bSeg) ^ bX);
            const uint32_t* ahp = &ph[kc*4];
            #pragma unroll
            for (int p = 0; p < 4; ++p) {
                uint32_t bh4[4], bl4[4];
                uint32_t ta = st + 16384 + (uint32_t)((2*p + ntHi)*1024) + kk;
                ldsm4(bh4, ta);
                ldsm4(bl4, ta + 8192);
                mma16816(oc[2*p],   ahp, bh4);
                mma16816(oc[2*p],   ahp, bl4);
                mma16816(oc[2*p+1], ahp, bh4+2);
                mma16816(oc[2*p+1], ahp, bl4+2);
            }
        }
        __syncthreads();
    }
    #undef STAGE

    // write partial O + partial row sums
    float* Og = g_O[s];
    const size_t ob0 = (size_t)(b*SS + q0 + w*16 + gid)*64;
    #pragma unroll
    for (int nt = 0; nt < 8; ++nt) {
        *(float2*)&Og[ob0 + nt*8 + tig*2]        = make_float2(oc[nt][0], oc[nt][1]);
        *(float2*)&Og[ob0 + 8*64 + nt*8 + tig*2] = make_float2(oc[nt][2], oc[nt][3]);
    }
    ls0 += __shfl_xor_sync(0xffffffffu, ls0, 1);
    ls0 += __shfl_xor_sync(0xffffffffu, ls0, 2);
    ls1 += __shfl_xor_sync(0xffffffffu, ls1, 1);
    ls1 += __shfl_xor_sync(0xffffffffu, ls1, 2);
    if (tig == 0) {
        g_L[s][b*SS + q0 + w*16 + gid]     = ls0;
        g_L[s][b*SS + q0 + w*16 + gid + 8] = ls1;
    }
}

// ---------------------------------------------------------------------------
// Kernel 3: combine split-k partials and normalize (float4).
// ---------------------------------------------------------------------------
__global__ __launch_bounds__(256) void finalize(float* __restrict__ out)
{
    int idx = blockIdx.x*256 + threadIdx.x;        // over NROW*16 float4s
    float4 a = ((const float4*)g_O[0])[idx];
    float4 c = ((const float4*)g_O[1])[idx];
    int row = idx >> 4;
    float linv = 1.f / (g_L[0][row] + g_L[1][row]);
    float4 r;
    r.x = (a.x + c.x) * linv;
    r.y = (a.y + c.y) * linv;
    r.z = (a.z + c.z) * linv;
    r.w = (a.w + c.w) * linv;
    ((float4*)out)[idx] = r;
}

// ---------------------------------------------------------------------------
extern "C" void kernel_launch(void* const* d_in, const int* in_sizes, int n_in,
                              void* d_out, int out_size)
{
    const float* X  = (const float*)d_in[0];
    const float* Wq = (const float*)d_in[1];
    const float* Wk = (const float*)d_in[2];
    const float* Wv = (const float*)d_in[3];
    float* out = (float*)d_out;

    prep_x<<<(NROW*512)/256, 256>>>(X);
    prep_w<<<384, 256>>>(Wq, Wk, Wv);

    const int qkv_smem = 131072;
    cudaFuncSetAttribute(qkv_mma,
                         cudaFuncAttributeMaxDynamicSharedMemorySize, qkv_smem);
    qkv_mma<<<128, 256, qkv_smem>>>();

    const int attn_smem = 65536;
    cudaFuncSetAttribute(attn_mma,
                         cudaFuncAttributeMaxDynamicSharedMemorySize, attn_smem);
    attn_mma<<<dim3(64, BB), 256, attn_smem>>>();

    finalize<<<(NROW*16)/256, 256>>>(out);
}

// round 10
// speedup vs baseline: 1.1148x; 1.1148x over previous
#include <cuda_runtime.h>
#include <cuda_fp16.h>
#include <cstdint>
#include <math.h>

#define BB 4
#define SS 4096
#define DD 1024
#define HH 64
#define NROW (BB*SS)
#define NSPL 4

// Q scale: 1/8 softmax scale * log2(e) for ex2-based exp
#define QSC 0.18033688011112042f

// ---------------- scratch (__device__ globals; allocation-free rule) -------
__device__ uint32_t g_Xh[NROW*512];                     // [row][d-pair] f16x2
__device__ uint32_t g_Qh[NROW*32];                      // [row][d-pair] f16x2
__device__ uint32_t g_Kh[NROW*32], g_Kl[NROW*32];       // [row][d-pair]
__device__ uint32_t g_Vth[BB*64*2048], g_Vtl[BB*64*2048]; // [b][h][seq-pair]
__device__ uint32_t g_Wth[192*512], g_Wtl[192*512];     // [n(=3*64)][d-pair]
__device__ float    g_O[NSPL][NROW*64];                 // split-k partial O
__device__ float    g_L[NSPL][NROW];                    // split-k partial rowsum

// ---------------- helpers --------------------------------------------------
__device__ __forceinline__ uint32_t smem_u32(const void* p){
    uint32_t a;
    asm("{ .reg .u64 t; cvta.to.shared.u64 t, %1; cvt.u32.u64 %0, t; }"
        : "=r"(a) : "l"(p));
    return a;
}
__device__ __forceinline__ void mma16816(float* d, const uint32_t* a,
                                         const uint32_t* b){
    asm volatile(
        "mma.sync.aligned.m16n8k16.row.col.f32.f16.f16.f32 "
        "{%0,%1,%2,%3}, {%4,%5,%6,%7}, {%8,%9}, {%0,%1,%2,%3};"
        : "+f"(d[0]), "+f"(d[1]), "+f"(d[2]), "+f"(d[3])
        : "r"(a[0]), "r"(a[1]), "r"(a[2]), "r"(a[3]), "r"(b[0]), "r"(b[1]));
}
__device__ __forceinline__ void ldsm4(uint32_t* r, uint32_t addr){
    asm volatile("ldmatrix.sync.aligned.m8n8.x4.shared.b16 {%0,%1,%2,%3}, [%4];"
        : "=r"(r[0]), "=r"(r[1]), "=r"(r[2]), "=r"(r[3]) : "r"(addr));
}
__device__ __forceinline__ void cpasync16(uint32_t dst, const void* src){
    asm volatile("cp.async.cg.shared.global [%0], [%1], 16;"
                 :: "r"(dst), "l"(src));
}
#define CP_COMMIT() asm volatile("cp.async.commit_group;" ::: "memory")
#define CP_WAIT1()  asm volatile("cp.async.wait_group 1;" ::: "memory")
#define CP_WAIT0()  asm volatile("cp.async.wait_group 0;" ::: "memory")

__device__ __forceinline__ float ex2(float x){
    float r; asm("ex2.approx.f32 %0, %1;" : "=f"(r) : "f"(x)); return r;
}
// fp16x2 pack: f0 -> low half, f1 -> high half
__device__ __forceinline__ uint32_t pack2h(float f0, float f1){
    uint32_t r;
    asm("cvt.rn.f16x2.f32 %0, %1, %2;" : "=r"(r) : "f"(f1), "f"(f0));
    return r;
}
// split-fp16: (f0,f1) -> hi f16x2 + lo residual f16x2
__device__ __forceinline__ void split2h(float f0, float f1,
                                        uint32_t& hv, uint32_t& lv){
    hv = pack2h(f0, f1);
    __half2 h = *reinterpret_cast<__half2*>(&hv);
    float h0 = __low2float(h), h1 = __high2float(h);
    lv = pack2h(f0 - h0, f1 - h1);
}
// swizzled byte offset inside a [row][128B] tile (conflict-free ldmatrix)
__device__ __forceinline__ uint32_t swz(int r, int bytecol){
    return (uint32_t)(r*128 + (bytecol ^ ((r & 7) << 4)));
}

// ---------------------------------------------------------------------------
// Kernel 0a: convert X -> fp16 pairs.  Kernel 0b: transpose+split W.
// ---------------------------------------------------------------------------
__global__ __launch_bounds__(256) void prep_x(const float* __restrict__ X){
    int idx = blockIdx.x*256 + threadIdx.x;
    float2 x = ((const float2*)X)[idx];
    g_Xh[idx] = pack2h(x.x, x.y);
}
__global__ __launch_bounds__(256) void prep_w(
    const float* __restrict__ Wq, const float* __restrict__ Wk,
    const float* __restrict__ Wv)
{
    int idx = blockIdx.x*256 + threadIdx.x;
    if (idx >= 192*512) return;
    int n = idx >> 9, dp = idx & 511;
    const float* W = (n < 64) ? Wq : (n < 128) ? Wk : Wv;
    int h = n & 63, d = dp*2;
    uint32_t hv, lv;
    split2h(W[d*64 + h], W[(d+1)*64 + h], hv, lv);
    g_Wth[idx] = hv;  g_Wtl[idx] = lv;
}

// ---------------------------------------------------------------------------
// Kernel 1: QKV via mma.sync fp16 2-term, COLUMN-SPLIT: grid (128, 3).
// blockIdx.y = reg (0=Q,1=K,2=V), CTA: 128 rows x 64 cols.
// smem per buffer: XH 16KB @0, WH 8KB @16384, WL 8KB @24576 -> 32KB;
// 2 buffers = 64KB dynamic -> 2-3 CTAs/SM.
// ---------------------------------------------------------------------------
extern __shared__ char dsm[];

__global__ __launch_bounds__(256) void qkv_mma()
{
    uint32_t sb = smem_u32(dsm);
    const int tid = threadIdx.x, w = tid >> 5, lane = tid & 31;
    const int gid = lane >> 2, tig = lane & 3;
    const int row0 = blockIdx.x * 128;
    const int reg  = blockIdx.y;                   // 0=Q 1=K 2=V
    const int mrow = w * 16;

    const int aR   = mrow + (lane & 7) + ((lane >> 3) & 1) * 8;
    const uint32_t aOff = (uint32_t)aR * 128;
    const int aSeg = (lane >> 4) ? 16 : 0;
    const uint32_t aX = (uint32_t)((lane & 7) << 4);
    const uint32_t bOff = (uint32_t)((lane & 7) * 128);
    const int bSeg = (lane & 8) ? 16 : 0;
    const uint32_t bX = (uint32_t)((lane & 7) << 4);
    const int ntHi = (lane >> 4) & 1;

    float acc[8][4];
    #pragma unroll
    for (int nt = 0; nt < 8; ++nt)
        #pragma unroll
        for (int j = 0; j < 4; ++j) acc[nt][j] = 0.f;

    #define QSTAGE(buf, kc) do {                                              \
        uint32_t _b = sb + (uint32_t)(buf)*32768;                             \
        _Pragma("unroll")                                                     \
        for (int _i = 0; _i < 4; ++_i) {                                      \
            int _idx = tid + 256*_i;               /* 1024: X 16B units */    \
            int _r = _idx >> 3, _c4 = _idx & 7;                               \
            uint32_t _o = swz(_r, _c4*16);                                    \
            cpasync16(_b + _o, g_Xh + (size_t)(row0+_r)*512 + (kc)*32 + _c4*4);\
        }                                                                     \
        {   /* W: 512 16B units x2 */                                         \
            int _idx = tid;                                                   \
            int _r = _idx >> 3, _c4 = _idx & 7;                               \
            uint32_t _o = swz(_r, _c4*16);                                    \
            if (_idx < 512) {                                                 \
                size_t _src = (size_t)(reg*64 + _r)*512 + (kc)*32 + _c4*4;    \
                cpasync16(_b + 16384 + _o, g_Wth + _src);                     \
                cpasync16(_b + 24576 + _o, g_Wtl + _src);                     \
            } else {                                                          \
                _idx -= 512? 0 : 0;                                           \
            }                                                                 \
        }                                                                     \
        {   int _idx = tid + 256;                                             \
            int _r = _idx >> 3, _c4 = _idx & 7;                               \
            uint32_t _o = swz(_r, _c4*16);                                    \
            size_t _src = (size_t)(reg*64 + _r)*512 + (kc)*32 + _c4*4;        \
            cpasync16(_b + 16384 + _o, g_Wth + _src);                         \
            cpasync16(_b + 24576 + _o, g_Wtl + _src);                         \
        }                                                                     \
        CP_COMMIT();                                                          \
    } while (0)

    QSTAGE(0, 0);

    for (int kc = 0; kc < 16; ++kc) {
        const bool more = (kc + 1 < 16);
        if (more) QSTAGE((kc+1) & 1, kc+1);
        if (more) CP_WAIT1(); else CP_WAIT0();
        __syncthreads();
        const uint32_t st = sb + (uint32_t)((kc & 1) * 32768);

        #pragma unroll
        for (int ks = 0; ks < 4; ++ks) {
            uint32_t ah[4];
            ldsm4(ah, st + aOff + (uint32_t)((ks*32 + aSeg) ^ aX));
            uint32_t kk = bOff + (uint32_t)((ks*32 + bSeg) ^ bX);
            #pragma unroll
            for (int p = 0; p < 4; ++p) {
                uint32_t bh4[4], bl4[4];
                uint32_t ta = st + 16384 + (uint32_t)((2*p + ntHi)*1024) + kk;
                ldsm4(bh4, ta);
                ldsm4(bl4, ta + 8192);
                mma16816(acc[2*p],   ah, bh4);
                mma16816(acc[2*p],   ah, bl4);
                mma16816(acc[2*p+1], ah, bh4+2);
                mma16816(acc[2*p+1], ah, bl4+2);
            }
        }
        __syncthreads();
    }
    #undef QSTAGE

    const int r0g = row0 + mrow + gid, r1g = r0g + 8;
    if (reg == 0) {
        // Q: scale, hi-only
        #pragma unroll
        for (int nt = 0; nt < 8; ++nt) {
            g_Qh[r0g*32 + nt*4 + tig] = pack2h(acc[nt][0]*QSC, acc[nt][1]*QSC);
            g_Qh[r1g*32 + nt*4 + tig] = pack2h(acc[nt][2]*QSC, acc[nt][3]*QSC);
        }
    } else if (reg == 1) {
        // K: split
        #pragma unroll
        for (int nt = 0; nt < 8; ++nt) {
            uint32_t hv, lv;
            split2h(acc[nt][0], acc[nt][1], hv, lv);
            g_Kh[r0g*32 + nt*4 + tig] = hv;  g_Kl[r0g*32 + nt*4 + tig] = lv;
            split2h(acc[nt][2], acc[nt][3], hv, lv);
            g_Kh[r1g*32 + nt*4 + tig] = hv;  g_Kl[r1g*32 + nt*4 + tig] = lv;
        }
    } else {
        // V: transpose via smem, split-write [b][h][seq-pair]
        float* Vt = (float*)dsm;                   // 64*128*4 = 32KB
        #pragma unroll
        for (int nt = 0; nt < 8; ++nt) {
            int h0 = nt*8 + tig*2;
            Vt[h0*128 + mrow + gid]         = acc[nt][0];
            Vt[(h0+1)*128 + mrow + gid]     = acc[nt][1];
            Vt[h0*128 + mrow + gid + 8]     = acc[nt][2];
            Vt[(h0+1)*128 + mrow + gid + 8] = acc[nt][3];
        }
        __syncthreads();
        const int bb = row0 >> 12, sloc = row0 & 4095;
        #pragma unroll
        for (int i = 0; i < 16; ++i) {
            int idx = tid + 256*i;
            int h = idx >> 6, sp = idx & 63;
            uint32_t hv, lv;
            split2h(Vt[h*128 + 2*sp], Vt[h*128 + 2*sp + 1], hv, lv);
            size_t o = (size_t)(bb*64 + h)*2048 + (sloc >> 1) + sp;
            g_Vth[o] = hv;  g_Vtl[o] = lv;
        }
    }
}

// ---------------------------------------------------------------------------
// Kernel 2: causal attention, fp16 2-term, no-max softmax, 4-way split-K.
// grid (128, 4): qq = 31 - (bx>>2) longest-first, s = bx&3; 512 CTAs.
// k-tiles kt = s + 4t, t < n = ceil((2qq+2-s)/4).
// cp.async double-buffered K/V staging (2 x 32KB dynamic smem).
// ---------------------------------------------------------------------------
__global__ __launch_bounds__(256) void attn_mma()
{
    uint32_t sb = smem_u32(dsm);
    const int tid = threadIdx.x, w = tid >> 5, lane = tid & 31;
    const int gid = lane >> 2, tig = lane & 3;
    const int qq = 31 - ((int)blockIdx.x >> 2);
    const int s  = blockIdx.x & 3;
    const int b  = blockIdx.y;
    const int q0 = qq * 128;
    const int n  = (2*qq + 2 - s + 3) >> 2;        // #k-tiles for this split

    const uint32_t bOff = (uint32_t)((lane & 7) * 128);
    const int bSeg = (lane & 8) ? 16 : 0;
    const uint32_t bX = (uint32_t)((lane & 7) << 4);
    const int ntHi = (lane >> 4) & 1;

    const uint32_t* KH = g_Kh + (size_t)(b*SS)*32;
    const uint32_t* KL = g_Kl + (size_t)(b*SS)*32;
    const uint32_t* VH = g_Vth + (size_t)(b*64)*2048;
    const uint32_t* VL = g_Vtl + (size_t)(b*64)*2048;

    // Q fragments (hi only, registers)
    const int r0g = b*SS + q0 + w*16 + gid, r1g = r0g + 8;
    uint32_t qf[4][4];
    #pragma unroll
    for (int ks = 0; ks < 4; ++ks) {
        qf[ks][0] = g_Qh[r0g*32 + ks*8 + tig];
        qf[ks][1] = g_Qh[r1g*32 + ks*8 + tig];
        qf[ks][2] = g_Qh[r0g*32 + ks*8 + 4 + tig];
        qf[ks][3] = g_Qh[r1g*32 + ks*8 + 4 + tig];
    }

    float oc[8][4];
    #pragma unroll
    for (int nt = 0; nt < 8; ++nt)
        #pragma unroll
        for (int c = 0; c < 4; ++c) oc[nt][c] = 0.f;
    float ls0 = 0.f, ls1 = 0.f;
    const int qg0 = q0 + w*16 + gid, qg1 = qg0 + 8;

    #define STAGE(buf, k0) do {                                               \
        uint32_t _b = sb + (uint32_t)(buf)*32768;                             \
        _Pragma("unroll")                                                     \
        for (int _i = 0; _i < 2; ++_i) {                                      \
            int _idx = tid + 256*_i;                                          \
            int _r = _idx >> 3, _c4 = _idx & 7;                               \
            uint32_t _o = swz(_r, _c4*16);                                    \
            cpasync16(_b + _o,         KH + (size_t)((k0)+_r)*32 + _c4*4);    \
            cpasync16(_b + 8192 + _o,  KL + (size_t)((k0)+_r)*32 + _c4*4);    \
            cpasync16(_b + 16384 + _o, VH + (size_t)_r*2048 + ((k0)>>1) + _c4*4);\
            cpasync16(_b + 24576 + _o, VL + (size_t)_r*2048 + ((k0)>>1) + _c4*4);\
        }                                                                     \
        CP_COMMIT();                                                          \
    } while (0)

    if (n > 0) {
        STAGE(0, s*64);

        for (int t = 0; t < n; ++t) {
            const int k0 = (s + 4*t) * 64;
            const bool more = (t + 1 < n);
            if (more) STAGE((t+1) & 1, (s + 4*(t+1))*64);
            if (more) CP_WAIT1(); else CP_WAIT0();
            __syncthreads();
            const uint32_t st = sb + (uint32_t)((t & 1) * 32768);

            // scores = Q_hi . (K_hi + K_lo)
            float sc[8][4];
            #pragma unroll
            for (int nt = 0; nt < 8; ++nt)
                #pragma unroll
                for (int c = 0; c < 4; ++c) sc[nt][c] = 0.f;
            #pragma unroll
            for (int ks = 0; ks < 4; ++ks) {
                uint32_t kk = bOff + (uint32_t)((ks*32 + bSeg) ^ bX);
                #pragma unroll
                for (int p = 0; p < 4; ++p) {
                    uint32_t bh4[4], bl4[4];
                    uint32_t ta = st + (uint32_t)((2*p + ntHi)*1024) + kk;
                    ldsm4(bh4, ta);
                    ldsm4(bl4, ta + 8192);
                    mma16816(sc[2*p],   qf[ks], bh4);
                    mma16816(sc[2*p],   qf[ks], bl4);
                    mma16816(sc[2*p+1], qf[ks], bh4+2);
                    mma16816(sc[2*p+1], qf[ks], bl4+2);
                }
            }

            // mask + exp2; P -> fp16 A-fragments
            uint32_t ph[16];
            #pragma unroll
            for (int nt = 0; nt < 8; ++nt) {
                int kg = k0 + nt*8 + tig*2;
                float p0 = (kg     <= qg0) ? ex2(sc[nt][0]) : 0.f;
                float p1 = (kg + 1 <= qg0) ? ex2(sc[nt][1]) : 0.f;
                float p2 = (kg     <= qg1) ? ex2(sc[nt][2]) : 0.f;
                float p3 = (kg + 1 <= qg1) ? ex2(sc[nt][3]) : 0.f;
                ls0 += p0 + p1;  ls1 += p2 + p3;
                ph[nt*2]     = pack2h(p0, p1);
                ph[nt*2 + 1] = pack2h(p2, p3);
            }

            // O += P_hi . (V_hi + V_lo)
            #pragma unroll
            for (int kc = 0; kc < 4; ++kc) {
                uint32_t kk = bOff + (uint32_t)((kc*32 + bSeg) ^ bX);
                const uint32_t* ahp = &ph[kc*4];
                #pragma unroll
                for (int p = 0; p < 4; ++p) {
                    uint32_t bh4[4], bl4[4];
                    uint32_t ta = st + 16384 + (uint32_t)((2*p + ntHi)*1024) + kk;
                    ldsm4(bh4, ta);
                    ldsm4(bl4, ta + 8192);
                    mma16816(oc[2*p],   ahp, bh4);
                    mma16816(oc[2*p],   ahp, bl4);
                    mma16816(oc[2*p+1], ahp, bh4+2);
                    mma16816(oc[2*p+1], ahp, bl4+2);
                }
            }
            __syncthreads();
        }
    }
    #undef STAGE

    // write partial O + partial row sums
    float* Og = g_O[s];
    const size_t ob0 = (size_t)(b*SS + q0 + w*16 + gid)*64;
    #pragma unroll
    for (int nt = 0; nt < 8; ++nt) {
        *(float2*)&Og[ob0 + nt*8 + tig*2]        = make_float2(oc[nt][0], oc[nt][1]);
        *(float2*)&Og[ob0 + 8*64 + nt*8 + tig*2] = make_float2(oc[nt][2], oc[nt][3]);
    }
    ls0 += __shfl_xor_sync(0xffffffffu, ls0, 1);
    ls0 += __shfl_xor_sync(0xffffffffu, ls0, 2);
    ls1 += __shfl_xor_sync(0xffffffffu, ls1, 1);
    ls1 += __shfl_xor_sync(0xffffffffu, ls1, 2);
    if (tig == 0) {
        g_L[s][b*SS + q0 + w*16 + gid]     = ls0;
        g_L[s][b*SS + q0 + w*16 + gid + 8] = ls1;
    }
}

// ---------------------------------------------------------------------------
// Kernel 3: combine 4 split-k partials and normalize (float4).
// ---------------------------------------------------------------------------
__global__ __launch_bounds__(256) void finalize(float* __restrict__ out)
{
    int idx = blockIdx.x*256 + threadIdx.x;        // over NROW*16 float4s
    int row = idx >> 4;
    float4 a = ((const float4*)g_O[0])[idx];
    float4 c = ((const float4*)g_O[1])[idx];
    float4 d = ((const float4*)g_O[2])[idx];
    float4 e = ((const float4*)g_O[3])[idx];
    float l = g_L[0][row] + g_L[1][row] + g_L[2][row] + g_L[3][row];
    float linv = 1.f / l;
    float4 r;
    r.x = (a.x + c.x + d.x + e.x) * linv;
    r.y = (a.y + c.y + d.y + e.y) * linv;
    r.z = (a.z + c.z + d.z + e.z) * linv;
    r.w = (a.w + c.w + d.w + e.w) * linv;
    ((float4*)out)[idx] = r;
}

// ---------------------------------------------------------------------------
extern "C" void kernel_launch(void* const* d_in, const int* in_sizes, int n_in,
                              void* d_out, int out_size)
{
    const float* X  = (const float*)d_in[0];
    const float* Wq = (const float*)d_in[1];
    const float* Wk = (const float*)d_in[2];
    const float* Wv = (const float*)d_in[3];
    float* out = (float*)d_out;

    prep_x<<<(NROW*512)/256, 256>>>(X);
    prep_w<<<384, 256>>>(Wq, Wk, Wv);

    const int qkv_smem = 65536;
    cudaFuncSetAttribute(qkv_mma,
                         cudaFuncAttributeMaxDynamicSharedMemorySize, qkv_smem);
    qkv_mma<<<dim3(128, 3), 256, qkv_smem>>>();

    const int attn_smem = 65536;
    cudaFuncSetAttribute(attn_mma,
                         cudaFuncAttributeMaxDynamicSharedMemorySize, attn_smem);
    attn_mma<<<dim3(128, BB), 256, attn_smem>>>();

    finalize<<<(NROW*16)/256, 256>>>(out);
}

// round 11
// speedup vs baseline: 1.3725x; 1.2312x over previous
#include <cuda_runtime.h>
#include <cuda_fp16.h>
#include <cstdint>
#include <math.h>

#define BB 4
#define SS 4096
#define DD 1024
#define HH 64
#define NROW (BB*SS)
#define NSPL 4

// Q scale: 1/8 softmax scale * log2(e) for ex2-based exp
#define QSC 0.18033688011112042f

// ---------------- scratch (__device__ globals; allocation-free rule) -------
__device__ uint32_t g_Xh[NROW*512];                     // [row][d-pair] f16x2
__device__ uint32_t g_Qh[NROW*32];                      // [row][d-pair] f16x2
__device__ uint32_t g_Kh[NROW*32];                      // [row][d-pair] (hi only)
__device__ uint32_t g_Vth[BB*64*2048];                  // [b][h][seq-pair] (hi only)
__device__ uint32_t g_Wth[192*512], g_Wtl[192*512];     // [n(=3*64)][d-pair]
__device__ float    g_O[NSPL][NROW*64];                 // split-k partial O
__device__ float    g_L[NSPL][NROW];                    // split-k partial rowsum

// ---------------- helpers --------------------------------------------------
__device__ __forceinline__ uint32_t smem_u32(const void* p){
    uint32_t a;
    asm("{ .reg .u64 t; cvta.to.shared.u64 t, %1; cvt.u32.u64 %0, t; }"
        : "=r"(a) : "l"(p));
    return a;
}
__device__ __forceinline__ void mma16816(float* d, const uint32_t* a,
                                         const uint32_t* b){
    asm volatile(
        "mma.sync.aligned.m16n8k16.row.col.f32.f16.f16.f32 "
        "{%0,%1,%2,%3}, {%4,%5,%6,%7}, {%8,%9}, {%0,%1,%2,%3};"
        : "+f"(d[0]), "+f"(d[1]), "+f"(d[2]), "+f"(d[3])
        : "r"(a[0]), "r"(a[1]), "r"(a[2]), "r"(a[3]), "r"(b[0]), "r"(b[1]));
}
__device__ __forceinline__ void ldsm4(uint32_t* r, uint32_t addr){
    asm volatile("ldmatrix.sync.aligned.m8n8.x4.shared.b16 {%0,%1,%2,%3}, [%4];"
        : "=r"(r[0]), "=r"(r[1]), "=r"(r[2]), "=r"(r[3]) : "r"(addr));
}
__device__ __forceinline__ void cpasync16(uint32_t dst, const void* src){
    asm volatile("cp.async.cg.shared.global [%0], [%1], 16;"
                 :: "r"(dst), "l"(src));
}
#define CP_COMMIT() asm volatile("cp.async.commit_group;" ::: "memory")
#define CP_WAIT1()  asm volatile("cp.async.wait_group 1;" ::: "memory")
#define CP_WAIT0()  asm volatile("cp.async.wait_group 0;" ::: "memory")

__device__ __forceinline__ float ex2(float x){
    float r; asm("ex2.approx.f32 %0, %1;" : "=f"(r) : "f"(x)); return r;
}
// fp16x2 pack: f0 -> low half, f1 -> high half
__device__ __forceinline__ uint32_t pack2h(float f0, float f1){
    uint32_t r;
    asm("cvt.rn.f16x2.f32 %0, %1, %2;" : "=r"(r) : "f"(f1), "f"(f0));
    return r;
}
// split-fp16: (f0,f1) -> hi f16x2 + lo residual f16x2
__device__ __forceinline__ void split2h(float f0, float f1,
                                        uint32_t& hv, uint32_t& lv){
    hv = pack2h(f0, f1);
    __half2 h = *reinterpret_cast<__half2*>(&hv);
    float h0 = __low2float(h), h1 = __high2float(h);
    lv = pack2h(f0 - h0, f1 - h1);
}
// swizzled byte offset inside a [row][128B] tile (conflict-free ldmatrix)
__device__ __forceinline__ uint32_t swz(int r, int bytecol){
    return (uint32_t)(r*128 + (bytecol ^ ((r & 7) << 4)));
}

// ---------------------------------------------------------------------------
// Kernel 0a: convert X -> fp16 pairs.  Kernel 0b: transpose+split W.
// ---------------------------------------------------------------------------
__global__ __launch_bounds__(256) void prep_x(const float* __restrict__ X){
    int idx = blockIdx.x*256 + threadIdx.x;
    float2 x = ((const float2*)X)[idx];
    g_Xh[idx] = pack2h(x.x, x.y);
}
__global__ __launch_bounds__(256) void prep_w(
    const float* __restrict__ Wq, const float* __restrict__ Wk,
    const float* __restrict__ Wv)
{
    int idx = blockIdx.x*256 + threadIdx.x;
    if (idx >= 192*512) return;
    int n = idx >> 9, dp = idx & 511;
    const float* W = (n < 64) ? Wq : (n < 128) ? Wk : Wv;
    int h = n & 63, d = dp*2;
    uint32_t hv, lv;
    split2h(W[d*64 + h], W[(d+1)*64 + h], hv, lv);
    g_Wth[idx] = hv;  g_Wtl[idx] = lv;
}

// ---------------------------------------------------------------------------
// Kernel 1: QKV via mma.sync fp16 2-term (A=X hi, B=W hi+lo), column-split.
// grid (128, 3): blockIdx.y = reg (0=Q,1=K,2=V).  CTA: 128 rows x 64 cols.
// smem per buffer: XH 16KB @0, WH 8KB @16384, WL 8KB @24576; x2 = 64KB.
// K and V epilogues write fp16 hi only.
// ---------------------------------------------------------------------------
extern __shared__ char dsm[];

__global__ __launch_bounds__(256) void qkv_mma()
{
    uint32_t sb = smem_u32(dsm);
    const int tid = threadIdx.x, w = tid >> 5, lane = tid & 31;
    const int gid = lane >> 2, tig = lane & 3;
    const int row0 = blockIdx.x * 128;
    const int reg  = blockIdx.y;                   // 0=Q 1=K 2=V
    const int mrow = w * 16;

    const int aR   = mrow + (lane & 7) + ((lane >> 3) & 1) * 8;
    const uint32_t aOff = (uint32_t)aR * 128;
    const int aSeg = (lane >> 4) ? 16 : 0;
    const uint32_t aX = (uint32_t)((lane & 7) << 4);
    const uint32_t bOff = (uint32_t)((lane & 7) * 128);
    const int bSeg = (lane & 8) ? 16 : 0;
    const uint32_t bX = (uint32_t)((lane & 7) << 4);
    const int ntHi = (lane >> 4) & 1;

    float acc[8][4];
    #pragma unroll
    for (int nt = 0; nt < 8; ++nt)
        #pragma unroll
        for (int j = 0; j < 4; ++j) acc[nt][j] = 0.f;

    #define QSTAGE(buf, kc) do {                                              \
        uint32_t _b = sb + (uint32_t)(buf)*32768;                             \
        _Pragma("unroll")                                                     \
        for (int _i = 0; _i < 4; ++_i) {                                      \
            int _idx = tid + 256*_i;               /* 1024: X 16B units */    \
            int _r = _idx >> 3, _c4 = _idx & 7;                               \
            uint32_t _o = swz(_r, _c4*16);                                    \
            cpasync16(_b + _o, g_Xh + (size_t)(row0+_r)*512 + (kc)*32 + _c4*4);\
        }                                                                     \
        _Pragma("unroll")                                                     \
        for (int _i = 0; _i < 2; ++_i) {           /* 512 W units x2 */       \
            int _idx = tid + 256*_i;                                          \
            int _r = _idx >> 3, _c4 = _idx & 7;                               \
            uint32_t _o = swz(_r, _c4*16);                                    \
            size_t _src = (size_t)(reg*64 + _r)*512 + (kc)*32 + _c4*4;        \
            cpasync16(_b + 16384 + _o, g_Wth + _src);                         \
            cpasync16(_b + 24576 + _o, g_Wtl + _src);                         \
        }                                                                     \
        CP_COMMIT();                                                          \
    } while (0)

    QSTAGE(0, 0);

    for (int kc = 0; kc < 16; ++kc) {
        const bool more = (kc + 1 < 16);
        if (more) QSTAGE((kc+1) & 1, kc+1);
        if (more) CP_WAIT1(); else CP_WAIT0();
        __syncthreads();
        const uint32_t st = sb + (uint32_t)((kc & 1) * 32768);

        #pragma unroll
        for (int ks = 0; ks < 4; ++ks) {
            uint32_t ah[4];
            ldsm4(ah, st + aOff + (uint32_t)((ks*32 + aSeg) ^ aX));
            uint32_t kk = bOff + (uint32_t)((ks*32 + bSeg) ^ bX);
            #pragma unroll
            for (int p = 0; p < 4; ++p) {
                uint32_t bh4[4], bl4[4];
                uint32_t ta = st + 16384 + (uint32_t)((2*p + ntHi)*1024) + kk;
                ldsm4(bh4, ta);
                ldsm4(bl4, ta + 8192);
                mma16816(acc[2*p],   ah, bh4);
                mma16816(acc[2*p],   ah, bl4);
                mma16816(acc[2*p+1], ah, bh4+2);
                mma16816(acc[2*p+1], ah, bl4+2);
            }
        }
        __syncthreads();
    }
    #undef QSTAGE

    const int r0g = row0 + mrow + gid, r1g = r0g + 8;
    if (reg == 0) {
        // Q: scale, hi-only
        #pragma unroll
        for (int nt = 0; nt < 8; ++nt) {
            g_Qh[r0g*32 + nt*4 + tig] = pack2h(acc[nt][0]*QSC, acc[nt][1]*QSC);
            g_Qh[r1g*32 + nt*4 + tig] = pack2h(acc[nt][2]*QSC, acc[nt][3]*QSC);
        }
    } else if (reg == 1) {
        // K: hi-only
        #pragma unroll
        for (int nt = 0; nt < 8; ++nt) {
            g_Kh[r0g*32 + nt*4 + tig] = pack2h(acc[nt][0], acc[nt][1]);
            g_Kh[r1g*32 + nt*4 + tig] = pack2h(acc[nt][2], acc[nt][3]);
        }
    } else {
        // V: transpose via smem, hi-only write [b][h][seq-pair]
        float* Vt = (float*)dsm;                   // 64*128*4 = 32KB
        #pragma unroll
        for (int nt = 0; nt < 8; ++nt) {
            int h0 = nt*8 + tig*2;
            Vt[h0*128 + mrow + gid]         = acc[nt][0];
            Vt[(h0+1)*128 + mrow + gid]     = acc[nt][1];
            Vt[h0*128 + mrow + gid + 8]     = acc[nt][2];
            Vt[(h0+1)*128 + mrow + gid + 8] = acc[nt][3];
        }
        __syncthreads();
        const int bb = row0 >> 12, sloc = row0 & 4095;
        #pragma unroll
        for (int i = 0; i < 16; ++i) {
            int idx = tid + 256*i;
            int h = idx >> 6, sp = idx & 63;
            size_t o = (size_t)(bb*64 + h)*2048 + (sloc >> 1) + sp;
            g_Vth[o] = pack2h(Vt[h*128 + 2*sp], Vt[h*128 + 2*sp + 1]);
        }
    }
}

// ---------------------------------------------------------------------------
// Kernel 2: causal attention, fp16 hi-only operands, no-max softmax,
// 4-way split-K.  grid (128, 4): qq = 31-(bx>>2) longest-first, s = bx&3.
// k-tiles kt = s+4t.  Double-buffered cp.async staging: per buffer
// KH 8KB @0, VH 8KB @8192 -> 16KB; x2 = 32KB dynamic.
// Causal mask evaluated only on tiles with k0 >= q0 (<=1 per split).
// ---------------------------------------------------------------------------
__global__ __launch_bounds__(256) void attn_mma()
{
    uint32_t sb = smem_u32(dsm);
    const int tid = threadIdx.x, w = tid >> 5, lane = tid & 31;
    const int gid = lane >> 2, tig = lane & 3;
    const int qq = 31 - ((int)blockIdx.x >> 2);
    const int s  = blockIdx.x & 3;
    const int b  = blockIdx.y;
    const int q0 = qq * 128;
    const int n  = (2*qq + 2 - s + 3) >> 2;        // #k-tiles for this split

    const uint32_t bOff = (uint32_t)((lane & 7) * 128);
    const int bSeg = (lane & 8) ? 16 : 0;
    const uint32_t bX = (uint32_t)((lane & 7) << 4);
    const int ntHi = (lane >> 4) & 1;

    const uint32_t* KH = g_Kh + (size_t)(b*SS)*32;
    const uint32_t* VH = g_Vth + (size_t)(b*64)*2048;

    // Q fragments (hi only, registers)
    const int r0g = b*SS + q0 + w*16 + gid, r1g = r0g + 8;
    uint32_t qf[4][4];
    #pragma unroll
    for (int ks = 0; ks < 4; ++ks) {
        qf[ks][0] = g_Qh[r0g*32 + ks*8 + tig];
        qf[ks][1] = g_Qh[r1g*32 + ks*8 + tig];
        qf[ks][2] = g_Qh[r0g*32 + ks*8 + 4 + tig];
        qf[ks][3] = g_Qh[r1g*32 + ks*8 + 4 + tig];
    }

    float oc[8][4];
    #pragma unroll
    for (int nt = 0; nt < 8; ++nt)
        #pragma unroll
        for (int c = 0; c < 4; ++c) oc[nt][c] = 0.f;
    float ls0 = 0.f, ls1 = 0.f;
    const int qg0 = q0 + w*16 + gid, qg1 = qg0 + 8;

    #define STAGE(buf, k0) do {                                               \
        uint32_t _b = sb + (uint32_t)(buf)*16384;                             \
        _Pragma("unroll")                                                     \
        for (int _i = 0; _i < 2; ++_i) {           /* 512 units x2 arrays */  \
            int _idx = tid + 256*_i;                                          \
            int _r = _idx >> 3, _c4 = _idx & 7;                               \
            uint32_t _o = swz(_r, _c4*16);                                    \
            cpasync16(_b + _o,        KH + (size_t)((k0)+_r)*32 + _c4*4);     \
            cpasync16(_b + 8192 + _o, VH + (size_t)_r*2048 + ((k0)>>1) + _c4*4);\
        }                                                                     \
        CP_COMMIT();                                                          \
    } while (0)

    if (n > 0) {
        STAGE(0, s*64);

        for (int t = 0; t < n; ++t) {
            const int k0 = (s + 4*t) * 64;
            const bool more = (t + 1 < n);
            if (more) STAGE((t+1) & 1, (s + 4*(t+1))*64);
            if (more) CP_WAIT1(); else CP_WAIT0();
            __syncthreads();
            const uint32_t st = sb + (uint32_t)((t & 1) * 16384);

            // scores = Q_hi . K_hi
            float sc[8][4];
            #pragma unroll
            for (int nt = 0; nt < 8; ++nt)
                #pragma unroll
                for (int c = 0; c < 4; ++c) sc[nt][c] = 0.f;
            #pragma unroll
            for (int ks = 0; ks < 4; ++ks) {
                uint32_t kk = bOff + (uint32_t)((ks*32 + bSeg) ^ bX);
                #pragma unroll
                for (int p = 0; p < 4; ++p) {
                    uint32_t bh4[4];
                    ldsm4(bh4, st + (uint32_t)((2*p + ntHi)*1024) + kk);
                    mma16816(sc[2*p],   qf[ks], bh4);
                    mma16816(sc[2*p+1], qf[ks], bh4+2);
                }
            }

            // exp2 (+ causal mask only on diagonal-overlap tiles)
            uint32_t ph[16];
            if (k0 >= q0) {
                #pragma unroll
                for (int nt = 0; nt < 8; ++nt) {
                    int kg = k0 + nt*8 + tig*2;
                    float p0 = (kg     <= qg0) ? ex2(sc[nt][0]) : 0.f;
                    float p1 = (kg + 1 <= qg0) ? ex2(sc[nt][1]) : 0.f;
                    float p2 = (kg     <= qg1) ? ex2(sc[nt][2]) : 0.f;
                    float p3 = (kg + 1 <= qg1) ? ex2(sc[nt][3]) : 0.f;
                    ls0 += p0 + p1;  ls1 += p2 + p3;
                    ph[nt*2]     = pack2h(p0, p1);
                    ph[nt*2 + 1] = pack2h(p2, p3);
                }
            } else {
                #pragma unroll
                for (int nt = 0; nt < 8; ++nt) {
                    float p0 = ex2(sc[nt][0]);
                    float p1 = ex2(sc[nt][1]);
                    float p2 = ex2(sc[nt][2]);
                    float p3 = ex2(sc[nt][3]);
                    ls0 += p0 + p1;  ls1 += p2 + p3;
                    ph[nt*2]     = pack2h(p0, p1);
                    ph[nt*2 + 1] = pack2h(p2, p3);
                }
            }

            // O += P_hi . V_hi
            #pragma unroll
            for (int kc = 0; kc < 4; ++kc) {
                uint32_t kk = bOff + (uint32_t)((kc*32 + bSeg) ^ bX);
                const uint32_t* ahp = &ph[kc*4];
                #pragma unroll
                for (int p = 0; p < 4; ++p) {
                    uint32_t bh4[4];
                    ldsm4(bh4, st + 8192 + (uint32_t)((2*p + ntHi)*1024) + kk);
                    mma16816(oc[2*p],   ahp, bh4);
                    mma16816(oc[2*p+1], ahp, bh4+2);
                }
            }
            __syncthreads();
        }
    }
    #undef STAGE

    // write partial O + partial row sums
    float* Og = g_O[s];
    const size_t ob0 = (size_t)(b*SS + q0 + w*16 + gid)*64;
    #pragma unroll
    for (int nt = 0; nt < 8; ++nt) {
        *(float2*)&Og[ob0 + nt*8 + tig*2]        = make_float2(oc[nt][0], oc[nt][1]);
        *(float2*)&Og[ob0 + 8*64 + nt*8 + tig*2] = make_float2(oc[nt][2], oc[nt][3]);
    }
    ls0 += __shfl_xor_sync(0xffffffffu, ls0, 1);
    ls0 += __shfl_xor_sync(0xffffffffu, ls0, 2);
    ls1 += __shfl_xor_sync(0xffffffffu, ls1, 1);
    ls1 += __shfl_xor_sync(0xffffffffu, ls1, 2);
    if (tig == 0) {
        g_L[s][b*SS + q0 + w*16 + gid]     = ls0;
        g_L[s][b*SS + q0 + w*16 + gid + 8] = ls1;
    }
}

// ---------------------------------------------------------------------------
// Kernel 3: combine 4 split-k partials and normalize (float4).
// ---------------------------------------------------------------------------
__global__ __launch_bounds__(256) void finalize(float* __restrict__ out)
{
    int idx = blockIdx.x*256 + threadIdx.x;        // over NROW*16 float4s
    int row = idx >> 4;
    float4 a = ((const float4*)g_O[0])[idx];
    float4 c = ((const float4*)g_O[1])[idx];
    float4 d = ((const float4*)g_O[2])[idx];
    float4 e = ((const float4*)g_O[3])[idx];
    float l = g_L[0][row] + g_L[1][row] + g_L[2][row] + g_L[3][row];
    float linv = 1.f / l;
    float4 r;
    r.x = (a.x + c.x + d.x + e.x) * linv;
    r.y = (a.y + c.y + d.y + e.y) * linv;
    r.z = (a.z + c.z + d.z + e.z) * linv;
    r.w = (a.w + c.w + d.w + e.w) * linv;
    ((float4*)out)[idx] = r;
}

// ---------------------------------------------------------------------------
extern "C" void kernel_launch(void* const* d_in, const int* in_sizes, int n_in,
                              void* d_out, int out_size)
{
    const float* X  = (const float*)d_in[0];
    const float* Wq = (const float*)d_in[1];
    const float* Wk = (const float*)d_in[2];
    const float* Wv = (const float*)d_in[3];
    float* out = (float*)d_out;

    prep_x<<<(NROW*512)/256, 256>>>(X);
    prep_w<<<384, 256>>>(Wq, Wk, Wv);

    const int qkv_smem = 65536;
    cudaFuncSetAttribute(qkv_mma,
                         cudaFuncAttributeMaxDynamicSharedMemorySize, qkv_smem);
    qkv_mma<<<dim3(128, 3), 256, qkv_smem>>>();

    const int attn_smem = 32768;
    cudaFuncSetAttribute(attn_mma,
                         cudaFuncAttributeMaxDynamicSharedMemorySize, attn_smem);
    attn_mma<<<dim3(128, BB), 256, attn_smem>>>();

    finalize<<<(NROW*16)/256, 256>>>(out);
}

// round 12
// speedup vs baseline: 1.6338x; 1.1904x over previous
#include <cuda_runtime.h>
#include <cuda_fp16.h>
#include <cstdint>
#include <math.h>

#define BB 4
#define SS 4096
#define DD 1024
#define HH 64
#define NROW (BB*SS)
#define NSPL 4

// Q scale: 1/8 softmax scale * log2(e) for ex2-based exp
#define QSC 0.18033688011112042f

// ---------------- scratch (__device__ globals; allocation-free rule) -------
__device__ uint32_t g_Xh[NROW*512];                     // [row][d-pair] f16x2
__device__ uint32_t g_Qh[NROW*32];                      // [row][d-pair] f16x2
__device__ uint32_t g_Kh[NROW*32];                      // [row][d-pair] (hi only)
__device__ uint32_t g_Vth[BB*64*2048];                  // [b][h][seq-pair] (hi only)
__device__ uint32_t g_Wth[192*512];                     // [n(=3*64)][d-pair] (hi only)
__device__ float    g_O[NSPL][NROW*64];                 // split-k partial O
__device__ float    g_L[NSPL][NROW];                    // split-k partial rowsum

// ---------------- helpers --------------------------------------------------
__device__ __forceinline__ uint32_t smem_u32(const void* p){
    uint32_t a;
    asm("{ .reg .u64 t; cvta.to.shared.u64 t, %1; cvt.u32.u64 %0, t; }"
        : "=r"(a) : "l"(p));
    return a;
}
__device__ __forceinline__ void mma16816(float* d, const uint32_t* a,
                                         const uint32_t* b){
    asm volatile(
        "mma.sync.aligned.m16n8k16.row.col.f32.f16.f16.f32 "
        "{%0,%1,%2,%3}, {%4,%5,%6,%7}, {%8,%9}, {%0,%1,%2,%3};"
        : "+f"(d[0]), "+f"(d[1]), "+f"(d[2]), "+f"(d[3])
        : "r"(a[0]), "r"(a[1]), "r"(a[2]), "r"(a[3]), "r"(b[0]), "r"(b[1]));
}
__device__ __forceinline__ void ldsm4(uint32_t* r, uint32_t addr){
    asm volatile("ldmatrix.sync.aligned.m8n8.x4.shared.b16 {%0,%1,%2,%3}, [%4];"
        : "=r"(r[0]), "=r"(r[1]), "=r"(r[2]), "=r"(r[3]) : "r"(addr));
}
__device__ __forceinline__ void cpasync16(uint32_t dst, const void* src){
    asm volatile("cp.async.cg.shared.global [%0], [%1], 16;"
                 :: "r"(dst), "l"(src));
}
#define CP_COMMIT() asm volatile("cp.async.commit_group;" ::: "memory")
#define CP_WAIT1()  asm volatile("cp.async.wait_group 1;" ::: "memory")
#define CP_WAIT0()  asm volatile("cp.async.wait_group 0;" ::: "memory")

__device__ __forceinline__ float ex2(float x){
    float r; asm("ex2.approx.f32 %0, %1;" : "=f"(r) : "f"(x)); return r;
}
// fp16x2 pack: f0 -> low half, f1 -> high half
__device__ __forceinline__ uint32_t pack2h(float f0, float f1){
    uint32_t r;
    asm("cvt.rn.f16x2.f32 %0, %1, %2;" : "=r"(r) : "f"(f1), "f"(f0));
    return r;
}
// swizzled byte offset inside a [row][128B] tile (conflict-free ldmatrix)
__device__ __forceinline__ uint32_t swz(int r, int bytecol){
    return (uint32_t)(r*128 + (bytecol ^ ((r & 7) << 4)));
}

// ---------------------------------------------------------------------------
// Kernel 0 (fused): X -> fp16 pairs  +  W transpose -> fp16 hi.
// blocks [0, 32768): X;  blocks [32768, 32768+384): W.
// ---------------------------------------------------------------------------
__global__ __launch_bounds__(256) void prep(
    const float* __restrict__ X,
    const float* __restrict__ Wq, const float* __restrict__ Wk,
    const float* __restrict__ Wv)
{
    int bid = blockIdx.x;
    if (bid < 32768) {
        int idx = bid*256 + threadIdx.x;
        float2 x = ((const float2*)X)[idx];
        g_Xh[idx] = pack2h(x.x, x.y);
    } else {
        int idx = (bid - 32768)*256 + threadIdx.x;
        if (idx >= 192*512) return;
        int n = idx >> 9, dp = idx & 511;
        const float* W = (n < 64) ? Wq : (n < 128) ? Wk : Wv;
        int h = n & 63, d = dp*2;
        g_Wth[idx] = pack2h(W[d*64 + h], W[(d+1)*64 + h]);
    }
}

// ---------------------------------------------------------------------------
// Kernel 1: QKV via mma.sync pure fp16 (A=X hi, B=W hi), column-split.
// grid (128, 3): blockIdx.y = reg (0=Q,1=K,2=V).  CTA: 128 rows x 64 cols.
// smem per buffer: XH 16KB @0, WH 8KB @16384 -> 24KB; x2 = 48KB dynamic.
// ---------------------------------------------------------------------------
extern __shared__ char dsm[];

__global__ __launch_bounds__(256) void qkv_mma()
{
    uint32_t sb = smem_u32(dsm);
    const int tid = threadIdx.x, w = tid >> 5, lane = tid & 31;
    const int gid = lane >> 2, tig = lane & 3;
    const int row0 = blockIdx.x * 128;
    const int reg  = blockIdx.y;                   // 0=Q 1=K 2=V
    const int mrow = w * 16;

    const int aR   = mrow + (lane & 7) + ((lane >> 3) & 1) * 8;
    const uint32_t aOff = (uint32_t)aR * 128;
    const int aSeg = (lane >> 4) ? 16 : 0;
    const uint32_t aX = (uint32_t)((lane & 7) << 4);
    const uint32_t bOff = (uint32_t)((lane & 7) * 128);
    const int bSeg = (lane & 8) ? 16 : 0;
    const uint32_t bX = (uint32_t)((lane & 7) << 4);
    const int ntHi = (lane >> 4) & 1;

    float acc[8][4];
    #pragma unroll
    for (int nt = 0; nt < 8; ++nt)
        #pragma unroll
        for (int j = 0; j < 4; ++j) acc[nt][j] = 0.f;

    #define QSTAGE(buf, kc) do {                                              \
        uint32_t _b = sb + (uint32_t)(buf)*24576;                             \
        _Pragma("unroll")                                                     \
        for (int _i = 0; _i < 4; ++_i) {           /* 1024: X 16B units */    \
            int _idx = tid + 256*_i;                                          \
            int _r = _idx >> 3, _c4 = _idx & 7;                               \
            uint32_t _o = swz(_r, _c4*16);                                    \
            cpasync16(_b + _o, g_Xh + (size_t)(row0+_r)*512 + (kc)*32 + _c4*4);\
        }                                                                     \
        _Pragma("unroll")                                                     \
        for (int _i = 0; _i < 2; ++_i) {           /* 512: W 16B units */     \
            int _idx = tid + 256*_i;                                          \
            int _r = _idx >> 3, _c4 = _idx & 7;                               \
            uint32_t _o = swz(_r, _c4*16);                                    \
            cpasync16(_b + 16384 + _o,                                        \
                      g_Wth + (size_t)(reg*64 + _r)*512 + (kc)*32 + _c4*4);   \
        }                                                                     \
        CP_COMMIT();                                                          \
    } while (0)

    QSTAGE(0, 0);

    for (int kc = 0; kc < 16; ++kc) {
        const bool more = (kc + 1 < 16);
        if (more) QSTAGE((kc+1) & 1, kc+1);
        if (more) CP_WAIT1(); else CP_WAIT0();
        __syncthreads();
        const uint32_t st = sb + (uint32_t)((kc & 1) * 24576);

        #pragma unroll
        for (int ks = 0; ks < 4; ++ks) {
            uint32_t ah[4];
            ldsm4(ah, st + aOff + (uint32_t)((ks*32 + aSeg) ^ aX));
            uint32_t kk = bOff + (uint32_t)((ks*32 + bSeg) ^ bX);
            #pragma unroll
            for (int p = 0; p < 4; ++p) {
                uint32_t bh4[4];
                ldsm4(bh4, st + 16384 + (uint32_t)((2*p + ntHi)*1024) + kk);
                mma16816(acc[2*p],   ah, bh4);
                mma16816(acc[2*p+1], ah, bh4+2);
            }
        }
        __syncthreads();
    }
    #undef QSTAGE

    const int r0g = row0 + mrow + gid, r1g = r0g + 8;
    if (reg == 0) {
        // Q: scale, hi-only
        #pragma unroll
        for (int nt = 0; nt < 8; ++nt) {
            g_Qh[r0g*32 + nt*4 + tig] = pack2h(acc[nt][0]*QSC, acc[nt][1]*QSC);
            g_Qh[r1g*32 + nt*4 + tig] = pack2h(acc[nt][2]*QSC, acc[nt][3]*QSC);
        }
    } else if (reg == 1) {
        // K: hi-only
        #pragma unroll
        for (int nt = 0; nt < 8; ++nt) {
            g_Kh[r0g*32 + nt*4 + tig] = pack2h(acc[nt][0], acc[nt][1]);
            g_Kh[r1g*32 + nt*4 + tig] = pack2h(acc[nt][2], acc[nt][3]);
        }
    } else {
        // V: transpose via smem, hi-only write [b][h][seq-pair]
        float* Vt = (float*)dsm;                   // 64*128*4 = 32KB
        #pragma unroll
        for (int nt = 0; nt < 8; ++nt) {
            int h0 = nt*8 + tig*2;
            Vt[h0*128 + mrow + gid]         = acc[nt][0];
            Vt[(h0+1)*128 + mrow + gid]     = acc[nt][1];
            Vt[h0*128 + mrow + gid + 8]     = acc[nt][2];
            Vt[(h0+1)*128 + mrow + gid + 8] = acc[nt][3];
        }
        __syncthreads();
        const int bb = row0 >> 12, sloc = row0 & 4095;
        #pragma unroll
        for (int i = 0; i < 16; ++i) {
            int idx = tid + 256*i;
            int h = idx >> 6, sp = idx & 63;
            size_t o = (size_t)(bb*64 + h)*2048 + (sloc >> 1) + sp;
            g_Vth[o] = pack2h(Vt[h*128 + 2*sp], Vt[h*128 + 2*sp + 1]);
        }
    }
}

// ---------------------------------------------------------------------------
// Kernel 2: causal attention, fp16 hi operands, no-max softmax, 4-way
// split-K.  grid (128, 4): qq = 31-(bx>>2) longest-first, s = bx&3.
// k-tiles kt = s+4t.  RING-OF-3 cp.async staging, ONE syncthreads per tile:
// per iter: {CP_WAIT; sync; STAGE(t+2); compute(t)}.
// per buffer: KH 8KB @0, VH 8KB @8192; x3 = 48KB dynamic.
// ---------------------------------------------------------------------------
__global__ __launch_bounds__(256) void attn_mma()
{
    uint32_t sb = smem_u32(dsm);
    const int tid = threadIdx.x, w = tid >> 5, lane = tid & 31;
    const int gid = lane >> 2, tig = lane & 3;
    const int qq = 31 - ((int)blockIdx.x >> 2);
    const int s  = blockIdx.x & 3;
    const int b  = blockIdx.y;
    const int q0 = qq * 128;
    const int n  = (2*qq + 2 - s + 3) >> 2;        // #k-tiles for this split

    const uint32_t bOff = (uint32_t)((lane & 7) * 128);
    const int bSeg = (lane & 8) ? 16 : 0;
    const uint32_t bX = (uint32_t)((lane & 7) << 4);
    const int ntHi = (lane >> 4) & 1;

    const uint32_t* KH = g_Kh + (size_t)(b*SS)*32;
    const uint32_t* VH = g_Vth + (size_t)(b*64)*2048;

    // Q fragments (hi only, registers)
    const int r0g = b*SS + q0 + w*16 + gid, r1g = r0g + 8;
    uint32_t qf[4][4];
    #pragma unroll
    for (int ks = 0; ks < 4; ++ks) {
        qf[ks][0] = g_Qh[r0g*32 + ks*8 + tig];
        qf[ks][1] = g_Qh[r1g*32 + ks*8 + tig];
        qf[ks][2] = g_Qh[r0g*32 + ks*8 + 4 + tig];
        qf[ks][3] = g_Qh[r1g*32 + ks*8 + 4 + tig];
    }

    float oc[8][4];
    #pragma unroll
    for (int nt = 0; nt < 8; ++nt)
        #pragma unroll
        for (int c = 0; c < 4; ++c) oc[nt][c] = 0.f;
    float ls0 = 0.f, ls1 = 0.f;
    const int qg0 = q0 + w*16 + gid, qg1 = qg0 + 8;

    #define STAGE(buf, k0) do {                                               \
        uint32_t _b = sb + (uint32_t)(buf)*16384;                             \
        _Pragma("unroll")                                                     \
        for (int _i = 0; _i < 2; ++_i) {           /* 512 units x2 arrays */  \
            int _idx = tid + 256*_i;                                          \
            int _r = _idx >> 3, _c4 = _idx & 7;                               \
            uint32_t _o = swz(_r, _c4*16);                                    \
            cpasync16(_b + _o,        KH + (size_t)((k0)+_r)*32 + _c4*4);     \
            cpasync16(_b + 8192 + _o, VH + (size_t)_r*2048 + ((k0)>>1) + _c4*4);\
        }                                                                     \
        CP_COMMIT();                                                          \
    } while (0)

    if (n > 0) {
        STAGE(0, s*64);
        if (n > 1) STAGE(1, (s+4)*64);

        int buf = 0;                                // t % 3
        for (int t = 0; t < n; ++t) {
            const int k0 = (s + 4*t) * 64;
            if (t + 1 < n) CP_WAIT1(); else CP_WAIT0();
            __syncthreads();
            if (t + 2 < n) {
                int nb = buf + 2; if (nb >= 3) nb -= 3;
                STAGE(nb, (s + 4*(t+2))*64);
            }
            const uint32_t st = sb + (uint32_t)(buf * 16384);

            // scores = Q_hi . K_hi
            float sc[8][4];
            #pragma unroll
            for (int nt = 0; nt < 8; ++nt)
                #pragma unroll
                for (int c = 0; c < 4; ++c) sc[nt][c] = 0.f;
            #pragma unroll
            for (int ks = 0; ks < 4; ++ks) {
                uint32_t kk = bOff + (uint32_t)((ks*32 + bSeg) ^ bX);
                #pragma unroll
                for (int p = 0; p < 4; ++p) {
                    uint32_t bh4[4];
                    ldsm4(bh4, st + (uint32_t)((2*p + ntHi)*1024) + kk);
                    mma16816(sc[2*p],   qf[ks], bh4);
                    mma16816(sc[2*p+1], qf[ks], bh4+2);
                }
            }

            // exp2 (+ causal mask only on diagonal-overlap tiles)
            uint32_t ph[16];
            if (k0 >= q0) {
                #pragma unroll
                for (int nt = 0; nt < 8; ++nt) {
                    int kg = k0 + nt*8 + tig*2;
                    float p0 = (kg     <= qg0) ? ex2(sc[nt][0]) : 0.f;
                    float p1 = (kg + 1 <= qg0) ? ex2(sc[nt][1]) : 0.f;
                    float p2 = (kg     <= qg1) ? ex2(sc[nt][2]) : 0.f;
                    float p3 = (kg + 1 <= qg1) ? ex2(sc[nt][3]) : 0.f;
                    ls0 += p0 + p1;  ls1 += p2 + p3;
                    ph[nt*2]     = pack2h(p0, p1);
                    ph[nt*2 + 1] = pack2h(p2, p3);
                }
            } else {
                #pragma unroll
                for (int nt = 0; nt < 8; ++nt) {
                    float p0 = ex2(sc[nt][0]);
                    float p1 = ex2(sc[nt][1]);
                    float p2 = ex2(sc[nt][2]);
                    float p3 = ex2(sc[nt][3]);
                    ls0 += p0 + p1;  ls1 += p2 + p3;
                    ph[nt*2]     = pack2h(p0, p1);
                    ph[nt*2 + 1] = pack2h(p2, p3);
                }
            }

            // O += P_hi . V_hi
            #pragma unroll
            for (int kc = 0; kc < 4; ++kc) {
                uint32_t kk = bOff + (uint32_t)((kc*32 + bSeg) ^ bX);
                const uint32_t* ahp = &ph[kc*4];
                #pragma unroll
                for (int p = 0; p < 4; ++p) {
                    uint32_t bh4[4];
                    ldsm4(bh4, st + 8192 + (uint32_t)((2*p + ntHi)*1024) + kk);
                    mma16816(oc[2*p],   ahp, bh4);
                    mma16816(oc[2*p+1], ahp, bh4+2);
                }
            }
            if (++buf >= 3) buf = 0;
        }
    }
    #undef STAGE

    // write partial O + partial row sums
    float* Og = g_O[s];
    const size_t ob0 = (size_t)(b*SS + q0 + w*16 + gid)*64;
    #pragma unroll
    for (int nt = 0; nt < 8; ++nt) {
        *(float2*)&Og[ob0 + nt*8 + tig*2]        = make_float2(oc[nt][0], oc[nt][1]);
        *(float2*)&Og[ob0 + 8*64 + nt*8 + tig*2] = make_float2(oc[nt][2], oc[nt][3]);
    }
    ls0 += __shfl_xor_sync(0xffffffffu, ls0, 1);
    ls0 += __shfl_xor_sync(0xffffffffu, ls0, 2);
    ls1 += __shfl_xor_sync(0xffffffffu, ls1, 1);
    ls1 += __shfl_xor_sync(0xffffffffu, ls1, 2);
    if (tig == 0) {
        g_L[s][b*SS + q0 + w*16 + gid]     = ls0;
        g_L[s][b*SS + q0 + w*16 + gid + 8] = ls1;
    }
}

// ---------------------------------------------------------------------------
// Kernel 3: combine 4 split-k partials and normalize (float4).
// ---------------------------------------------------------------------------
__global__ __launch_bounds__(256) void finalize(float* __restrict__ out)
{
    int idx = blockIdx.x*256 + threadIdx.x;        // over NROW*16 float4s
    int row = idx >> 4;
    float4 a = ((const float4*)g_O[0])[idx];
    float4 c = ((const float4*)g_O[1])[idx];
    float4 d = ((const float4*)g_O[2])[idx];
    float4 e = ((const float4*)g_O[3])[idx];
    float l = g_L[0][row] + g_L[1][row] + g_L[2][row] + g_L[3][row];
    float linv = 1.f / l;
    float4 r;
    r.x = (a.x + c.x + d.x + e.x) * linv;
    r.y = (a.y + c.y + d.y + e.y) * linv;
    r.z = (a.z + c.z + d.z + e.z) * linv;
    r.w = (a.w + c.w + d.w + e.w) * linv;
    ((float4*)out)[idx] = r;
}

// ---------------------------------------------------------------------------
extern "C" void kernel_launch(void* const* d_in, const int* in_sizes, int n_in,
                              void* d_out, int out_size)
{
    const float* X  = (const float*)d_in[0];
    const float* Wq = (const float*)d_in[1];
    const float* Wk = (const float*)d_in[2];
    const float* Wv = (const float*)d_in[3];
    float* out = (float*)d_out;

    prep<<<32768 + 384, 256>>>(X, Wq, Wk, Wv);

    const int qkv_smem = 49152;
    cudaFuncSetAttribute(qkv_mma,
                         cudaFuncAttributeMaxDynamicSharedMemorySize, qkv_smem);
    qkv_mma<<<dim3(128, 3), 256, qkv_smem>>>();

    const int attn_smem = 49152;
    cudaFuncSetAttribute(attn_mma,
                         cudaFuncAttributeMaxDynamicSharedMemorySize, attn_smem);
    attn_mma<<<dim3(128, BB), 256, attn_smem>>>();

    finalize<<<(NROW*16)/256, 256>>>(out);
}

// round 13
// speedup vs baseline: 1.7884x; 1.0946x over previous
#include <cuda_runtime.h>
#include <cuda_fp16.h>
#include <cstdint>
#include <math.h>

#define BB 4
#define SS 4096
#define DD 1024
#define HH 64
#define NROW (BB*SS)
#define NSPL 4

// Q scale: 1/8 softmax scale * log2(e) for ex2-based exp
#define QSC 0.18033688011112042f

// ---------------- scratch (__device__ globals; allocation-free rule) -------
__device__ uint32_t g_Qh[NROW*32];                      // [row][d-pair] f16x2
__device__ uint32_t g_Kh[NROW*32];                      // [row][d-pair] (hi only)
__device__ uint32_t g_Vth[BB*64*2048];                  // [b][h][seq-pair] (hi only)
__device__ uint32_t g_Wth[192*512];                     // [n(=3*64)][d-pair] (hi only)
__device__ uint32_t g_Oh[NSPL][NROW*32];                // split-k partial O, f16x2
__device__ float    g_L[NSPL][NROW];                    // split-k partial rowsum

// ---------------- helpers --------------------------------------------------
__device__ __forceinline__ uint32_t smem_u32(const void* p){
    uint32_t a;
    asm("{ .reg .u64 t; cvta.to.shared.u64 t, %1; cvt.u32.u64 %0, t; }"
        : "=r"(a) : "l"(p));
    return a;
}
__device__ __forceinline__ void mma16816(float* d, const uint32_t* a,
                                         const uint32_t* b){
    asm volatile(
        "mma.sync.aligned.m16n8k16.row.col.f32.f16.f16.f32 "
        "{%0,%1,%2,%3}, {%4,%5,%6,%7}, {%8,%9}, {%0,%1,%2,%3};"
        : "+f"(d[0]), "+f"(d[1]), "+f"(d[2]), "+f"(d[3])
        : "r"(a[0]), "r"(a[1]), "r"(a[2]), "r"(a[3]), "r"(b[0]), "r"(b[1]));
}
__device__ __forceinline__ void ldsm4(uint32_t* r, uint32_t addr){
    asm volatile("ldmatrix.sync.aligned.m8n8.x4.shared.b16 {%0,%1,%2,%3}, [%4];"
        : "=r"(r[0]), "=r"(r[1]), "=r"(r[2]), "=r"(r[3]) : "r"(addr));
}
__device__ __forceinline__ void cpasync16(uint32_t dst, const void* src){
    asm volatile("cp.async.cg.shared.global [%0], [%1], 16;"
                 :: "r"(dst), "l"(src));
}
#define CP_COMMIT() asm volatile("cp.async.commit_group;" ::: "memory")
#define CP_WAIT1()  asm volatile("cp.async.wait_group 1;" ::: "memory")
#define CP_WAIT0()  asm volatile("cp.async.wait_group 0;" ::: "memory")

__device__ __forceinline__ float ex2(float x){
    float r; asm("ex2.approx.f32 %0, %1;" : "=f"(r) : "f"(x)); return r;
}
// fp16x2 pack: f0 -> low half, f1 -> high half
__device__ __forceinline__ uint32_t pack2h(float f0, float f1){
    uint32_t r;
    asm("cvt.rn.f16x2.f32 %0, %1, %2;" : "=r"(r) : "f"(f1), "f"(f0));
    return r;
}
// swizzled byte offset inside a [row][128B] tile (conflict-free ldmatrix)
__device__ __forceinline__ uint32_t swz(int r, int bytecol){
    return (uint32_t)(r*128 + (bytecol ^ ((r & 7) << 4)));
}

// ---------------------------------------------------------------------------
// Kernel 0: W transpose -> fp16 hi.  (X conversion is fused into qkv_mma.)
// ---------------------------------------------------------------------------
__global__ __launch_bounds__(256) void prep_w(
    const float* __restrict__ Wq, const float* __restrict__ Wk,
    const float* __restrict__ Wv)
{
    int idx = blockIdx.x*256 + threadIdx.x;
    if (idx >= 192*512) return;
    int n = idx >> 9, dp = idx & 511;
    const float* W = (n < 64) ? Wq : (n < 128) ? Wk : Wv;
    int h = n & 63, d = dp*2;
    g_Wth[idx] = pack2h(W[d*64 + h], W[(d+1)*64 + h]);
}

// ---------------------------------------------------------------------------
// Kernel 1: QKV via mma.sync pure fp16, column-split, X converted inline.
// grid (128, 3): blockIdx.y = reg (0=Q,1=K,2=V).  CTA: 128 rows x 64 cols.
// smem: Xf16 16KB @0 (single buffer, guarded by the 2 per-chunk syncs);
//       W double buffer 8KB @16384 / @24576.  Total 32KB dynamic.
// X fp32 is prefetched one chunk ahead into registers (16 x LDG float2).
// ---------------------------------------------------------------------------
extern __shared__ char dsm[];

__global__ __launch_bounds__(256) void qkv_mma(const float* __restrict__ X)
{
    uint32_t sb = smem_u32(dsm);
    const int tid = threadIdx.x, w = tid >> 5, lane = tid & 31;
    const int gid = lane >> 2, tig = lane & 3;
    const int row0 = blockIdx.x * 128;
    const int reg  = blockIdx.y;                   // 0=Q 1=K 2=V
    const int mrow = w * 16;

    const int aR   = mrow + (lane & 7) + ((lane >> 3) & 1) * 8;
    const uint32_t aOff = (uint32_t)aR * 128;
    const int aSeg = (lane >> 4) ? 16 : 0;
    const uint32_t aX = (uint32_t)((lane & 7) << 4);
    const uint32_t bOff = (uint32_t)((lane & 7) * 128);
    const int bSeg = (lane & 8) ? 16 : 0;
    const uint32_t bX = (uint32_t)((lane & 7) << 4);
    const int ntHi = (lane >> 4) & 1;

    // per-thread X addressing: idx = tid + 256*i -> r = idx>>5, cp = idx&31
    const int xr_r  = tid >> 5;                    // row advances by 8 per i
    const int xr_cp = tid & 31;

    float acc[8][4];
    #pragma unroll
    for (int nt = 0; nt < 8; ++nt)
        #pragma unroll
        for (int j = 0; j < 4; ++j) acc[nt][j] = 0.f;

    #define WSTAGE(buf, kc) do {                                              \
        uint32_t _b = sb + 16384u + (uint32_t)(buf)*8192;                     \
        _Pragma("unroll")                                                     \
        for (int _i = 0; _i < 2; ++_i) {           /* 512: W 16B units */     \
            int _idx = tid + 256*_i;                                          \
            int _r = _idx >> 3, _c4 = _idx & 7;                               \
            uint32_t _o = swz(_r, _c4*16);                                    \
            cpasync16(_b + _o,                                                \
                      g_Wth + (size_t)(reg*64 + _r)*512 + (kc)*32 + _c4*4);   \
        }                                                                     \
        CP_COMMIT();                                                          \
    } while (0)

    // prefetch chunk 0 fp32 X into registers; stage W chunk 0
    float2 xr[16];
    #pragma unroll
    for (int i = 0; i < 16; ++i)
        xr[i] = *(const float2*)(X + (size_t)(row0 + xr_r + 8*i)*DD + 2*xr_cp);
    WSTAGE(0, 0);

    for (int kc = 0; kc < 16; ++kc) {
        __syncthreads();                           // A: prior MMA done
        // convert + store this chunk's X into the f16 buffer
        #pragma unroll
        for (int i = 0; i < 16; ++i) {
            uint32_t off = swz(xr_r + 8*i, xr_cp*4);
            *(uint32_t*)(dsm + off) = pack2h(xr[i].x, xr[i].y);
        }
        if (kc + 1 < 16) {
            WSTAGE((kc+1) & 1, kc+1);
            // prefetch next chunk's fp32 X (consumed next iteration)
            #pragma unroll
            for (int i = 0; i < 16; ++i)
                xr[i] = *(const float2*)(X + (size_t)(row0 + xr_r + 8*i)*DD
                                           + (kc+1)*64 + 2*xr_cp);
            CP_WAIT1();
        } else {
            CP_WAIT0();
        }
        __syncthreads();                           // B: STS + W(kc) visible

        const uint32_t wbase = sb + 16384u + (uint32_t)((kc & 1) * 8192);
        #pragma unroll
        for (int ks = 0; ks < 4; ++ks) {
            uint32_t ah[4];
            ldsm4(ah, sb + aOff + (uint32_t)((ks*32 + aSeg) ^ aX));
            uint32_t kk = bOff + (uint32_t)((ks*32 + bSeg) ^ bX);
            #pragma unroll
            for (int p = 0; p < 4; ++p) {
                uint32_t bh4[4];
                ldsm4(bh4, wbase + (uint32_t)((2*p + ntHi)*1024) + kk);
                mma16816(acc[2*p],   ah, bh4);
                mma16816(acc[2*p+1], ah, bh4+2);
            }
        }
    }
    #undef WSTAGE

    __syncthreads();
    const int r0g = row0 + mrow + gid, r1g = r0g + 8;
    if (reg == 0) {
        // Q: scale, hi-only
        #pragma unroll
        for (int nt = 0; nt < 8; ++nt) {
            g_Qh[r0g*32 + nt*4 + tig] = pack2h(acc[nt][0]*QSC, acc[nt][1]*QSC);
            g_Qh[r1g*32 + nt*4 + tig] = pack2h(acc[nt][2]*QSC, acc[nt][3]*QSC);
        }
    } else if (reg == 1) {
        // K: hi-only
        #pragma unroll
        for (int nt = 0; nt < 8; ++nt) {
            g_Kh[r0g*32 + nt*4 + tig] = pack2h(acc[nt][0], acc[nt][1]);
            g_Kh[r1g*32 + nt*4 + tig] = pack2h(acc[nt][2], acc[nt][3]);
        }
    } else {
        // V: transpose via smem (32KB), hi-only write [b][h][seq-pair]
        float* Vt = (float*)dsm;
        #pragma unroll
        for (int nt = 0; nt < 8; ++nt) {
            int h0 = nt*8 + tig*2;
            Vt[h0*128 + mrow + gid]         = acc[nt][0];
            Vt[(h0+1)*128 + mrow + gid]     = acc[nt][1];
            Vt[h0*128 + mrow + gid + 8]     = acc[nt][2];
            Vt[(h0+1)*128 + mrow + gid + 8] = acc[nt][3];
        }
        __syncthreads();
        const int bb = row0 >> 12, sloc = row0 & 4095;
        #pragma unroll
        for (int i = 0; i < 16; ++i) {
            int idx = tid + 256*i;
            int h = idx >> 6, sp = idx & 63;
            size_t o = (size_t)(bb*64 + h)*2048 + (sloc >> 1) + sp;
            g_Vth[o] = pack2h(Vt[h*128 + 2*sp], Vt[h*128 + 2*sp + 1]);
        }
    }
}

// ---------------------------------------------------------------------------
// Kernel 2: causal attention, fp16 hi operands, no-max softmax, 4-way
// split-K.  grid (128, 4): qq = 31-(bx>>2) longest-first, s = bx&3.
// k-tiles kt = s+4t.  RING-OF-3 cp.async staging, ONE syncthreads per tile.
// per buffer: KH 8KB @0, VH 8KB @8192; x3 = 48KB dynamic.
// Partial O written as f16x2.
// ---------------------------------------------------------------------------
__global__ __launch_bounds__(256) void attn_mma()
{
    uint32_t sb = smem_u32(dsm);
    const int tid = threadIdx.x, w = tid >> 5, lane = tid & 31;
    const int gid = lane >> 2, tig = lane & 3;
    const int qq = 31 - ((int)blockIdx.x >> 2);
    const int s  = blockIdx.x & 3;
    const int b  = blockIdx.y;
    const int q0 = qq * 128;
    const int n  = (2*qq + 2 - s + 3) >> 2;        // #k-tiles for this split

    const uint32_t bOff = (uint32_t)((lane & 7) * 128);
    const int bSeg = (lane & 8) ? 16 : 0;
    const uint32_t bX = (uint32_t)((lane & 7) << 4);
    const int ntHi = (lane >> 4) & 1;

    const uint32_t* KH = g_Kh + (size_t)(b*SS)*32;
    const uint32_t* VH = g_Vth + (size_t)(b*64)*2048;

    // Q fragments (hi only, registers)
    const int r0g = b*SS + q0 + w*16 + gid, r1g = r0g + 8;
    uint32_t qf[4][4];
    #pragma unroll
    for (int ks = 0; ks < 4; ++ks) {
        qf[ks][0] = g_Qh[r0g*32 + ks*8 + tig];
        qf[ks][1] = g_Qh[r1g*32 + ks*8 + tig];
        qf[ks][2] = g_Qh[r0g*32 + ks*8 + 4 + tig];
        qf[ks][3] = g_Qh[r1g*32 + ks*8 + 4 + tig];
    }

    float oc[8][4];
    #pragma unroll
    for (int nt = 0; nt < 8; ++nt)
        #pragma unroll
        for (int c = 0; c < 4; ++c) oc[nt][c] = 0.f;
    float ls0 = 0.f, ls1 = 0.f;
    const int qg0 = q0 + w*16 + gid, qg1 = qg0 + 8;

    #define STAGE(buf, k0) do {                                               \
        uint32_t _b = sb + (uint32_t)(buf)*16384;                             \
        _Pragma("unroll")                                                     \
        for (int _i = 0; _i < 2; ++_i) {           /* 512 units x2 arrays */  \
            int _idx = tid + 256*_i;                                          \
            int _r = _idx >> 3, _c4 = _idx & 7;                               \
            uint32_t _o = swz(_r, _c4*16);                                    \
            cpasync16(_b + _o,        KH + (size_t)((k0)+_r)*32 + _c4*4);     \
            cpasync16(_b + 8192 + _o, VH + (size_t)_r*2048 + ((k0)>>1) + _c4*4);\
        }                                                                     \
        CP_COMMIT();                                                          \
    } while (0)

    if (n > 0) {
        STAGE(0, s*64);
        if (n > 1) STAGE(1, (s+4)*64);

        int buf = 0;                                // t % 3
        for (int t = 0; t < n; ++t) {
            const int k0 = (s + 4*t) * 64;
            if (t + 1 < n) CP_WAIT1(); else CP_WAIT0();
            __syncthreads();
            if (t + 2 < n) {
                int nb = buf + 2; if (nb >= 3) nb -= 3;
                STAGE(nb, (s + 4*(t+2))*64);
            }
            const uint32_t st = sb + (uint32_t)(buf * 16384);

            // scores = Q_hi . K_hi
            float sc[8][4];
            #pragma unroll
            for (int nt = 0; nt < 8; ++nt)
                #pragma unroll
                for (int c = 0; c < 4; ++c) sc[nt][c] = 0.f;
            #pragma unroll
            for (int ks = 0; ks < 4; ++ks) {
                uint32_t kk = bOff + (uint32_t)((ks*32 + bSeg) ^ bX);
                #pragma unroll
                for (int p = 0; p < 4; ++p) {
                    uint32_t bh4[4];
                    ldsm4(bh4, st + (uint32_t)((2*p + ntHi)*1024) + kk);
                    mma16816(sc[2*p],   qf[ks], bh4);
                    mma16816(sc[2*p+1], qf[ks], bh4+2);
                }
            }

            // exp2 (+ causal mask only on diagonal-overlap tiles)
            uint32_t ph[16];
            if (k0 >= q0) {
                #pragma unroll
                for (int nt = 0; nt < 8; ++nt) {
                    int kg = k0 + nt*8 + tig*2;
                    float p0 = (kg     <= qg0) ? ex2(sc[nt][0]) : 0.f;
                    float p1 = (kg + 1 <= qg0) ? ex2(sc[nt][1]) : 0.f;
                    float p2 = (kg     <= qg1) ? ex2(sc[nt][2]) : 0.f;
                    float p3 = (kg + 1 <= qg1) ? ex2(sc[nt][3]) : 0.f;
                    ls0 += p0 + p1;  ls1 += p2 + p3;
                    ph[nt*2]     = pack2h(p0, p1);
                    ph[nt*2 + 1] = pack2h(p2, p3);
                }
            } else {
                #pragma unroll
                for (int nt = 0; nt < 8; ++nt) {
                    float p0 = ex2(sc[nt][0]);
                    float p1 = ex2(sc[nt][1]);
                    float p2 = ex2(sc[nt][2]);
                    float p3 = ex2(sc[nt][3]);
                    ls0 += p0 + p1;  ls1 += p2 + p3;
                    ph[nt*2]     = pack2h(p0, p1);
                    ph[nt*2 + 1] = pack2h(p2, p3);
                }
            }

            // O += P_hi . V_hi
            #pragma unroll
            for (int kc = 0; kc < 4; ++kc) {
                uint32_t kk = bOff + (uint32_t)((kc*32 + bSeg) ^ bX);
                const uint32_t* ahp = &ph[kc*4];
                #pragma unroll
                for (int p = 0; p < 4; ++p) {
                    uint32_t bh4[4];
                    ldsm4(bh4, st + 8192 + (uint32_t)((2*p + ntHi)*1024) + kk);
                    mma16816(oc[2*p],   ahp, bh4);
                    mma16816(oc[2*p+1], ahp, bh4+2);
                }
            }
            if (++buf >= 3) buf = 0;
        }
    }
    #undef STAGE

    // write partial O (f16x2) + partial row sums
    uint32_t* Og = g_Oh[s];
    const size_t ob0 = (size_t)(b*SS + q0 + w*16 + gid)*32;
    #pragma unroll
    for (int nt = 0; nt < 8; ++nt) {
        Og[ob0 + nt*4 + tig]        = pack2h(oc[nt][0], oc[nt][1]);
        Og[ob0 + 8*32 + nt*4 + tig] = pack2h(oc[nt][2], oc[nt][3]);
    }
    ls0 += __shfl_xor_sync(0xffffffffu, ls0, 1);
    ls0 += __shfl_xor_sync(0xffffffffu, ls0, 2);
    ls1 += __shfl_xor_sync(0xffffffffu, ls1, 1);
    ls1 += __shfl_xor_sync(0xffffffffu, ls1, 2);
    if (tig == 0) {
        g_L[s][b*SS + q0 + w*16 + gid]     = ls0;
        g_L[s][b*SS + q0 + w*16 + gid + 8] = ls1;
    }
}

// ---------------------------------------------------------------------------
// Kernel 3: combine 4 f16x2 split-k partials and normalize.
// One thread per column-pair -> float2 output.
// ---------------------------------------------------------------------------
__global__ __launch_bounds__(256) void finalize(float* __restrict__ out)
{
    int idx = blockIdx.x*256 + threadIdx.x;        // over NROW*32 pairs
    int row = idx >> 5;
    float l = g_L[0][row] + g_L[1][row] + g_L[2][row] + g_L[3][row];
    float linv = 1.f / l;
    float s0 = 0.f, s1 = 0.f;
    #pragma unroll
    for (int k = 0; k < NSPL; ++k) {
        uint32_t v = g_Oh[k][idx];
        __half2 h = *reinterpret_cast<__half2*>(&v);
        s0 += __low2float(h);
        s1 += __high2float(h);
    }
    ((float2*)out)[idx] = make_float2(s0*linv, s1*linv);
}

// ---------------------------------------------------------------------------
extern "C" void kernel_launch(void* const* d_in, const int* in_sizes, int n_in,
                              void* d_out, int out_size)
{
    const float* X  = (const float*)d_in[0];
    const float* Wq = (const float*)d_in[1];
    const float* Wk = (const float*)d_in[2];
    const float* Wv = (const float*)d_in[3];
    float* out = (float*)d_out;

    prep_w<<<384, 256>>>(Wq, Wk, Wv);

    const int qkv_smem = 32768;
    cudaFuncSetAttribute(qkv_mma,
                         cudaFuncAttributeMaxDynamicSharedMemorySize, qkv_smem);
    qkv_mma<<<dim3(128, 3), 256, qkv_smem>>>(X);

    const int attn_smem = 49152;
    cudaFuncSetAttribute(attn_mma,
                         cudaFuncAttributeMaxDynamicSharedMemorySize, attn_smem);
    attn_mma<<<dim3(128, BB), 256, attn_smem>>>();

    finalize<<<(NROW*32)/256, 256>>>(out);
}

// round 14
// speedup vs baseline: 1.8320x; 1.0244x over previous
#include <cuda_runtime.h>
#include <cuda_fp16.h>
#include <cstdint>
#include <math.h>

#define BB 4
#define SS 4096
#define DD 1024
#define HH 64
#define NROW (BB*SS)
#define NSPL 4

// Q scale: 1/8 softmax scale * log2(e) for ex2-based exp
#define QSC 0.18033688011112042f

// ---------------- scratch (__device__ globals; allocation-free rule) -------
__device__ uint32_t g_Qh[NROW*32];                      // [row][d-pair] f16x2
__device__ uint32_t g_Kh[NROW*32];                      // [row][d-pair] (hi only)
__device__ uint32_t g_Vth[BB*64*2048];                  // [b][h][seq-pair] (hi only)
__device__ uint32_t g_Wth[192*512];                     // [n(=3*64)][d-pair] (hi only)
__device__ uint32_t g_Oh[NSPL][NROW*32];                // split-k partial O, f16x2
__device__ float    g_L[NSPL][NROW];                    // split-k partial rowsum

// ---------------- helpers --------------------------------------------------
__device__ __forceinline__ uint32_t smem_u32(const void* p){
    uint32_t a;
    asm("{ .reg .u64 t; cvta.to.shared.u64 t, %1; cvt.u32.u64 %0, t; }"
        : "=r"(a) : "l"(p));
    return a;
}
__device__ __forceinline__ void mma16816(float* d, const uint32_t* a,
                                         const uint32_t* b){
    asm volatile(
        "mma.sync.aligned.m16n8k16.row.col.f32.f16.f16.f32 "
        "{%0,%1,%2,%3}, {%4,%5,%6,%7}, {%8,%9}, {%0,%1,%2,%3};"
        : "+f"(d[0]), "+f"(d[1]), "+f"(d[2]), "+f"(d[3])
        : "r"(a[0]), "r"(a[1]), "r"(a[2]), "r"(a[3]), "r"(b[0]), "r"(b[1]));
}
__device__ __forceinline__ void ldsm4(uint32_t* r, uint32_t addr){
    asm volatile("ldmatrix.sync.aligned.m8n8.x4.shared.b16 {%0,%1,%2,%3}, [%4];"
        : "=r"(r[0]), "=r"(r[1]), "=r"(r[2]), "=r"(r[3]) : "r"(addr));
}
__device__ __forceinline__ void cpasync16(uint32_t dst, const void* src){
    asm volatile("cp.async.cg.shared.global [%0], [%1], 16;"
                 :: "r"(dst), "l"(src));
}
#define CP_COMMIT() asm volatile("cp.async.commit_group;" ::: "memory")
#define CP_WAIT1()  asm volatile("cp.async.wait_group 1;" ::: "memory")
#define CP_WAIT0()  asm volatile("cp.async.wait_group 0;" ::: "memory")

__device__ __forceinline__ float ex2(float x){
    float r; asm("ex2.approx.f32 %0, %1;" : "=f"(r) : "f"(x)); return r;
}
// fp16x2 pack: f0 -> low half, f1 -> high half
__device__ __forceinline__ uint32_t pack2h(float f0, float f1){
    uint32_t r;
    asm("cvt.rn.f16x2.f32 %0, %1, %2;" : "=r"(r) : "f"(f1), "f"(f0));
    return r;
}
// swizzled byte offset inside a [row][128B] tile (conflict-free ldmatrix)
__device__ __forceinline__ uint32_t swz(int r, int bytecol){
    return (uint32_t)(r*128 + (bytecol ^ ((r & 7) << 4)));
}

// ---------------------------------------------------------------------------
// Kernel 0: W transpose -> fp16 hi.  (X conversion is fused into qkv_mma.)
// ---------------------------------------------------------------------------
__global__ __launch_bounds__(256) void prep_w(
    const float* __restrict__ Wq, const float* __restrict__ Wk,
    const float* __restrict__ Wv)
{
    int idx = blockIdx.x*256 + threadIdx.x;
    if (idx >= 192*512) return;
    int n = idx >> 9, dp = idx & 511;
    const float* W = (n < 64) ? Wq : (n < 128) ? Wk : Wv;
    int h = n & 63, d = dp*2;
    g_Wth[idx] = pack2h(W[d*64 + h], W[(d+1)*64 + h]);
}

// ---------------------------------------------------------------------------
// Kernel 1: QKV via mma.sync pure fp16, column-split, X converted inline.
// grid (128, 3): blockIdx.y = reg (0=Q,1=K,2=V).  CTA: 128 rows x 64 cols.
// smem: Xf16 16KB @0 (single buffer); W double buffer 8KB @16384/@24576.
// X fp32 prefetched one chunk ahead into registers.
// ---------------------------------------------------------------------------
extern __shared__ char dsm[];

__global__ __launch_bounds__(256) void qkv_mma(const float* __restrict__ X)
{
    uint32_t sb = smem_u32(dsm);
    const int tid = threadIdx.x, w = tid >> 5, lane = tid & 31;
    const int gid = lane >> 2, tig = lane & 3;
    const int row0 = blockIdx.x * 128;
    const int reg  = blockIdx.y;                   // 0=Q 1=K 2=V
    const int mrow = w * 16;

    const int aR   = mrow + (lane & 7) + ((lane >> 3) & 1) * 8;
    const uint32_t aOff = (uint32_t)aR * 128;
    const int aSeg = (lane >> 4) ? 16 : 0;
    const uint32_t aX = (uint32_t)((lane & 7) << 4);
    const uint32_t bOff = (uint32_t)((lane & 7) * 128);
    const int bSeg = (lane & 8) ? 16 : 0;
    const uint32_t bX = (uint32_t)((lane & 7) << 4);
    const int ntHi = (lane >> 4) & 1;

    const int xr_r  = tid >> 5;
    const int xr_cp = tid & 31;

    float acc[8][4];
    #pragma unroll
    for (int nt = 0; nt < 8; ++nt)
        #pragma unroll
        for (int j = 0; j < 4; ++j) acc[nt][j] = 0.f;

    #define WSTAGE(buf, kc) do {                                              \
        uint32_t _b = sb + 16384u + (uint32_t)(buf)*8192;                     \
        _Pragma("unroll")                                                     \
        for (int _i = 0; _i < 2; ++_i) {                                      \
            int _idx = tid + 256*_i;                                          \
            int _r = _idx >> 3, _c4 = _idx & 7;                               \
            uint32_t _o = swz(_r, _c4*16);                                    \
            cpasync16(_b + _o,                                                \
                      g_Wth + (size_t)(reg*64 + _r)*512 + (kc)*32 + _c4*4);   \
        }                                                                     \
        CP_COMMIT();                                                          \
    } while (0)

    float2 xr[16];
    #pragma unroll
    for (int i = 0; i < 16; ++i)
        xr[i] = *(const float2*)(X + (size_t)(row0 + xr_r + 8*i)*DD + 2*xr_cp);
    WSTAGE(0, 0);

    for (int kc = 0; kc < 16; ++kc) {
        __syncthreads();                           // A: prior MMA done
        #pragma unroll
        for (int i = 0; i < 16; ++i) {
            uint32_t off = swz(xr_r + 8*i, xr_cp*4);
            *(uint32_t*)(dsm + off) = pack2h(xr[i].x, xr[i].y);
        }
        if (kc + 1 < 16) {
            WSTAGE((kc+1) & 1, kc+1);
            #pragma unroll
            for (int i = 0; i < 16; ++i)
                xr[i] = *(const float2*)(X + (size_t)(row0 + xr_r + 8*i)*DD
                                           + (kc+1)*64 + 2*xr_cp);
            CP_WAIT1();
        } else {
            CP_WAIT0();
        }
        __syncthreads();                           // B: STS + W(kc) visible

        const uint32_t wbase = sb + 16384u + (uint32_t)((kc & 1) * 8192);
        #pragma unroll
        for (int ks = 0; ks < 4; ++ks) {
            uint32_t ah[4];
            ldsm4(ah, sb + aOff + (uint32_t)((ks*32 + aSeg) ^ aX));
            uint32_t kk = bOff + (uint32_t)((ks*32 + bSeg) ^ bX);
            #pragma unroll
            for (int p = 0; p < 4; ++p) {
                uint32_t bh4[4];
                ldsm4(bh4, wbase + (uint32_t)((2*p + ntHi)*1024) + kk);
                mma16816(acc[2*p],   ah, bh4);
                mma16816(acc[2*p+1], ah, bh4+2);
            }
        }
    }
    #undef WSTAGE

    __syncthreads();
    const int r0g = row0 + mrow + gid, r1g = r0g + 8;
    if (reg == 0) {
        #pragma unroll
        for (int nt = 0; nt < 8; ++nt) {
            g_Qh[r0g*32 + nt*4 + tig] = pack2h(acc[nt][0]*QSC, acc[nt][1]*QSC);
            g_Qh[r1g*32 + nt*4 + tig] = pack2h(acc[nt][2]*QSC, acc[nt][3]*QSC);
        }
    } else if (reg == 1) {
        #pragma unroll
        for (int nt = 0; nt < 8; ++nt) {
            g_Kh[r0g*32 + nt*4 + tig] = pack2h(acc[nt][0], acc[nt][1]);
            g_Kh[r1g*32 + nt*4 + tig] = pack2h(acc[nt][2], acc[nt][3]);
        }
    } else {
        float* Vt = (float*)dsm;
        #pragma unroll
        for (int nt = 0; nt < 8; ++nt) {
            int h0 = nt*8 + tig*2;
            Vt[h0*128 + mrow + gid]         = acc[nt][0];
            Vt[(h0+1)*128 + mrow + gid]     = acc[nt][1];
            Vt[h0*128 + mrow + gid + 8]     = acc[nt][2];
            Vt[(h0+1)*128 + mrow + gid + 8] = acc[nt][3];
        }
        __syncthreads();
        const int bb = row0 >> 12, sloc = row0 & 4095;
        #pragma unroll
        for (int i = 0; i < 16; ++i) {
            int idx = tid + 256*i;
            int h = idx >> 6, sp = idx & 63;
            size_t o = (size_t)(bb*64 + h)*2048 + (sloc >> 1) + sp;
            g_Vth[o] = pack2h(Vt[h*128 + 2*sp], Vt[h*128 + 2*sp + 1]);
        }
    }
}

// ---------------------------------------------------------------------------
// Kernel 2: causal attention, fp16 hi operands, no-max softmax, 4-way
// split-K.  grid (128, 4): qq = 31-(bx>>2) longest-first, s = bx&3.
// TWO k-tiles per pipeline stage (128 keys/stage): ring-of-3 x 32KB = 96KB,
// ONE syncthreads + ONE cp.async group per stage (pair of tiles).
// Stage layout: [K_a 8K][V_a 8K][K_b 8K][V_b 8K].
// ---------------------------------------------------------------------------
__global__ __launch_bounds__(256) void attn_mma()
{
    uint32_t sb = smem_u32(dsm);
    const int tid = threadIdx.x, w = tid >> 5, lane = tid & 31;
    const int gid = lane >> 2, tig = lane & 3;
    const int qq = 31 - ((int)blockIdx.x >> 2);
    const int s  = blockIdx.x & 3;
    const int b  = blockIdx.y;
    const int q0 = qq * 128;
    const int n  = (2*qq + 2 - s + 3) >> 2;        // #k-tiles for this split
    const int npair = (n + 1) >> 1;                // pipeline stages

    const uint32_t bOff = (uint32_t)((lane & 7) * 128);
    const int bSeg = (lane & 8) ? 16 : 0;
    const uint32_t bX = (uint32_t)((lane & 7) << 4);
    const int ntHi = (lane >> 4) & 1;

    const uint32_t* KH = g_Kh + (size_t)(b*SS)*32;
    const uint32_t* VH = g_Vth + (size_t)(b*64)*2048;

    // Q fragments (hi only, registers)
    const int r0g = b*SS + q0 + w*16 + gid, r1g = r0g + 8;
    uint32_t qf[4][4];
    #pragma unroll
    for (int ks = 0; ks < 4; ++ks) {
        qf[ks][0] = g_Qh[r0g*32 + ks*8 + tig];
        qf[ks][1] = g_Qh[r1g*32 + ks*8 + tig];
        qf[ks][2] = g_Qh[r0g*32 + ks*8 + 4 + tig];
        qf[ks][3] = g_Qh[r1g*32 + ks*8 + 4 + tig];
    }

    float oc[8][4];
    #pragma unroll
    for (int nt = 0; nt < 8; ++nt)
        #pragma unroll
        for (int c = 0; c < 4; ++c) oc[nt][c] = 0.f;
    float ls0 = 0.f, ls1 = 0.f;
    const int qg0 = q0 + w*16 + gid, qg1 = qg0 + 8;

    // stage a PAIR of k-tiles (t0 = 2u, t1 = 2u+1); t1 staged only if valid
    #define STAGE(buf, u) do {                                                \
        uint32_t _b = sb + (uint32_t)(buf)*32768;                             \
        int _t0 = 2*(u);                                                      \
        int _k0 = (s + 4*_t0) * 64;                                           \
        _Pragma("unroll")                                                     \
        for (int _i = 0; _i < 2; ++_i) {                                      \
            int _idx = tid + 256*_i;                                          \
            int _r = _idx >> 3, _c4 = _idx & 7;                               \
            uint32_t _o = swz(_r, _c4*16);                                    \
            cpasync16(_b + _o,        KH + (size_t)(_k0+_r)*32 + _c4*4);      \
            cpasync16(_b + 8192 + _o, VH + (size_t)_r*2048 + (_k0>>1) + _c4*4);\
        }                                                                     \
        if (_t0 + 1 < n) {                                                    \
            int _k1 = _k0 + 256;                                              \
            _Pragma("unroll")                                                 \
            for (int _i = 0; _i < 2; ++_i) {                                  \
                int _idx = tid + 256*_i;                                      \
                int _r = _idx >> 3, _c4 = _idx & 7;                           \
                uint32_t _o = swz(_r, _c4*16);                                \
                cpasync16(_b + 16384 + _o, KH + (size_t)(_k1+_r)*32 + _c4*4); \
                cpasync16(_b + 24576 + _o,                                    \
                          VH + (size_t)_r*2048 + (_k1>>1) + _c4*4);           \
            }                                                                 \
        }                                                                     \
        CP_COMMIT();                                                          \
    } while (0)

    // compute one 64-key subtile at smem offset stoff, key base k0c
    #define COMPUTE(stoff, k0c) do {                                          \
        float sc[8][4];                                                       \
        _Pragma("unroll")                                                     \
        for (int nt = 0; nt < 8; ++nt)                                        \
            _Pragma("unroll")                                                 \
            for (int c = 0; c < 4; ++c) sc[nt][c] = 0.f;                      \
        _Pragma("unroll")                                                     \
        for (int ks = 0; ks < 4; ++ks) {                                      \
            uint32_t kk = bOff + (uint32_t)((ks*32 + bSeg) ^ bX);             \
            _Pragma("unroll")                                                 \
            for (int p = 0; p < 4; ++p) {                                     \
                uint32_t bh4[4];                                              \
                ldsm4(bh4, (stoff) + (uint32_t)((2*p + ntHi)*1024) + kk);     \
                mma16816(sc[2*p],   qf[ks], bh4);                             \
                mma16816(sc[2*p+1], qf[ks], bh4+2);                           \
            }                                                                 \
        }                                                                     \
        uint32_t ph[16];                                                      \
        if ((k0c) >= q0) {                                                    \
            _Pragma("unroll")                                                 \
            for (int nt = 0; nt < 8; ++nt) {                                  \
                int kg = (k0c) + nt*8 + tig*2;                                \
                float p0 = (kg     <= qg0) ? ex2(sc[nt][0]) : 0.f;            \
                float p1 = (kg + 1 <= qg0) ? ex2(sc[nt][1]) : 0.f;            \
                float p2 = (kg     <= qg1) ? ex2(sc[nt][2]) : 0.f;            \
                float p3 = (kg + 1 <= qg1) ? ex2(sc[nt][3]) : 0.f;            \
                ls0 += p0 + p1;  ls1 += p2 + p3;                              \
                ph[nt*2]     = pack2h(p0, p1);                                \
                ph[nt*2 + 1] = pack2h(p2, p3);                                \
            }                                                                 \
        } else {                                                              \
            _Pragma("unroll")                                                 \
            for (int nt = 0; nt < 8; ++nt) {                                  \
                float p0 = ex2(sc[nt][0]);                                    \
                float p1 = ex2(sc[nt][1]);                                    \
                float p2 = ex2(sc[nt][2]);                                    \
                float p3 = ex2(sc[nt][3]);                                    \
                ls0 += p0 + p1;  ls1 += p2 + p3;                              \
                ph[nt*2]     = pack2h(p0, p1);                                \
                ph[nt*2 + 1] = pack2h(p2, p3);                                \
            }                                                                 \
        }                                                                     \
        _Pragma("unroll")                                                     \
        for (int kc = 0; kc < 4; ++kc) {                                      \
            uint32_t kk = bOff + (uint32_t)((kc*32 + bSeg) ^ bX);             \
            const uint32_t* ahp = &ph[kc*4];                                  \
            _Pragma("unroll")                                                 \
            for (int p = 0; p < 4; ++p) {                                     \
                uint32_t bh4[4];                                              \
                ldsm4(bh4, (stoff) + 8192 + (uint32_t)((2*p + ntHi)*1024) + kk);\
                mma16816(oc[2*p],   ahp, bh4);                                \
                mma16816(oc[2*p+1], ahp, bh4+2);                              \
            }                                                                 \
        }                                                                     \
    } while (0)

    if (npair > 0) {
        STAGE(0, 0);
        if (npair > 1) STAGE(1, 1);

        int buf = 0;                                // u % 3
        for (int u = 0; u < npair; ++u) {
            if (u + 1 < npair) CP_WAIT1(); else CP_WAIT0();
            __syncthreads();
            if (u + 2 < npair) {
                int nb = buf + 2; if (nb >= 3) nb -= 3;
                STAGE(nb, u + 2);
            }
            const uint32_t st = sb + (uint32_t)(buf * 32768);
            const int t0 = 2*u;
            const int k0a = (s + 4*t0) * 64;
            COMPUTE(st, k0a);
            if (t0 + 1 < n) {
                COMPUTE(st + 16384, k0a + 256);
            }
            if (++buf >= 3) buf = 0;
        }
    }
    #undef STAGE
    #undef COMPUTE

    // write partial O (f16x2) + partial row sums
    uint32_t* Og = g_Oh[s];
    const size_t ob0 = (size_t)(b*SS + q0 + w*16 + gid)*32;
    #pragma unroll
    for (int nt = 0; nt < 8; ++nt) {
        Og[ob0 + nt*4 + tig]        = pack2h(oc[nt][0], oc[nt][1]);
        Og[ob0 + 8*32 + nt*4 + tig] = pack2h(oc[nt][2], oc[nt][3]);
    }
    ls0 += __shfl_xor_sync(0xffffffffu, ls0, 1);
    ls0 += __shfl_xor_sync(0xffffffffu, ls0, 2);
    ls1 += __shfl_xor_sync(0xffffffffu, ls1, 1);
    ls1 += __shfl_xor_sync(0xffffffffu, ls1, 2);
    if (tig == 0) {
        g_L[s][b*SS + q0 + w*16 + gid]     = ls0;
        g_L[s][b*SS + q0 + w*16 + gid + 8] = ls1;
    }
}

// ---------------------------------------------------------------------------
// Kernel 3: combine 4 f16x2 split-k partials and normalize.
// Each thread: 2 pairs (LDG.64 x4, STG.128).
// ---------------------------------------------------------------------------
__global__ __launch_bounds__(256) void finalize(float* __restrict__ out)
{
    int idx = blockIdx.x*256 + threadIdx.x;        // over NROW*16 pair-duos
    int row = idx >> 4;
    float l = g_L[0][row] + g_L[1][row] + g_L[2][row] + g_L[3][row];
    float linv = 1.f / l;
    float s0 = 0.f, s1 = 0.f, s2 = 0.f, s3 = 0.f;
    #pragma unroll
    for (int k = 0; k < NSPL; ++k) {
        uint2 v = ((const uint2*)g_Oh[k])[idx];
        __half2 h0 = *reinterpret_cast<__half2*>(&v.x);
        __half2 h1 = *reinterpret_cast<__half2*>(&v.y);
        s0 += __low2float(h0);  s1 += __high2float(h0);
        s2 += __low2float(h1);  s3 += __high2float(h1);
    }
    ((float4*)out)[idx] = make_float4(s0*linv, s1*linv, s2*linv, s3*linv);
}

// ---------------------------------------------------------------------------
extern "C" void kernel_launch(void* const* d_in, const int* in_sizes, int n_in,
                              void* d_out, int out_size)
{
    const float* X  = (const float*)d_in[0];
    const float* Wq = (const float*)d_in[1];
    const float* Wk = (const float*)d_in[2];
    const float* Wv = (const float*)d_in[3];
    float* out = (float*)d_out;

    prep_w<<<384, 256>>>(Wq, Wk, Wv);

    const int qkv_smem = 32768;
    cudaFuncSetAttribute(qkv_mma,
                         cudaFuncAttributeMaxDynamicSharedMemorySize, qkv_smem);
    qkv_mma<<<dim3(128, 3), 256, qkv_smem>>>(X);

    const int attn_smem = 98304;
    cudaFuncSetAttribute(attn_mma,
                         cudaFuncAttributeMaxDynamicSharedMemorySize, attn_smem);
    attn_mma<<<dim3(128, BB), 256, attn_smem>>>();

    finalize<<<(NROW*16)/256, 256>>>(out);
}

// round 15
// speedup vs baseline: 2.1873x; 1.1939x over previous
#include <cuda_runtime.h>
#include <cuda_fp16.h>
#include <cstdint>
#include <math.h>

#define BB 4
#define SS 4096
#define DD 1024
#define HH 64
#define NROW (BB*SS)
#define NSPL 4

// Q scale: 1/8 softmax scale * log2(e) for ex2-based exp
#define QSC 0.18033688011112042f

// ---------------- scratch (__device__ globals; allocation-free rule) -------
__device__ uint32_t g_Qh[NROW*32];                      // [row][d-pair] f16x2
__device__ uint32_t g_Kh[NROW*32];                      // [row][d-pair] (hi only)
__device__ uint32_t g_Vth[BB*64*2048];                  // [b][h][seq-pair] (hi only)
__device__ uint32_t g_Wth[192*512];                     // [n(=3*64)][d-pair] (hi only)
__device__ uint32_t g_Oh[NSPL][NROW*32];                // split-k partial O, f16x2
__device__ float    g_L[NSPL][NROW];                    // split-k partial rowsum

// ---------------- helpers --------------------------------------------------
__device__ __forceinline__ uint32_t smem_u32(const void* p){
    uint32_t a;
    asm("{ .reg .u64 t; cvta.to.shared.u64 t, %1; cvt.u32.u64 %0, t; }"
        : "=r"(a) : "l"(p));
    return a;
}
__device__ __forceinline__ void mma16816(float* d, const uint32_t* a,
                                         const uint32_t* b){
    asm volatile(
        "mma.sync.aligned.m16n8k16.row.col.f32.f16.f16.f32 "
        "{%0,%1,%2,%3}, {%4,%5,%6,%7}, {%8,%9}, {%0,%1,%2,%3};"
        : "+f"(d[0]), "+f"(d[1]), "+f"(d[2]), "+f"(d[3])
        : "r"(a[0]), "r"(a[1]), "r"(a[2]), "r"(a[3]), "r"(b[0]), "r"(b[1]));
}
__device__ __forceinline__ void ldsm4(uint32_t* r, uint32_t addr){
    asm volatile("ldmatrix.sync.aligned.m8n8.x4.shared.b16 {%0,%1,%2,%3}, [%4];"
        : "=r"(r[0]), "=r"(r[1]), "=r"(r[2]), "=r"(r[3]) : "r"(addr));
}
__device__ __forceinline__ void cpasync16(uint32_t dst, const void* src){
    asm volatile("cp.async.cg.shared.global [%0], [%1], 16;"
                 :: "r"(dst), "l"(src));
}
#define CP_COMMIT() asm volatile("cp.async.commit_group;" ::: "memory")
#define CP_WAIT1()  asm volatile("cp.async.wait_group 1;" ::: "memory")
#define CP_WAIT0()  asm volatile("cp.async.wait_group 0;" ::: "memory")

// fp16x2 pack: f0 -> low half, f1 -> high half
__device__ __forceinline__ uint32_t pack2h(float f0, float f1){
    uint32_t r;
    asm("cvt.rn.f16x2.f32 %0, %1, %2;" : "=r"(r) : "f"(f1), "f"(f0));
    return r;
}
// packed fp16x2 exp2
__device__ __forceinline__ uint32_t h2ex2(uint32_t x){
    uint32_t r;
    asm("ex2.approx.f16x2 %0, %1;" : "=r"(r) : "r"(x));
    return r;
}
// swizzled byte offset inside a [row][128B] tile (conflict-free ldmatrix)
__device__ __forceinline__ uint32_t swz(int r, int bytecol){
    return (uint32_t)(r*128 + (bytecol ^ ((r & 7) << 4)));
}

// ---------------------------------------------------------------------------
// Kernel 0: W transpose -> fp16 hi.
// ---------------------------------------------------------------------------
__global__ __launch_bounds__(256) void prep_w(
    const float* __restrict__ Wq, const float* __restrict__ Wk,
    const float* __restrict__ Wv)
{
    int idx = blockIdx.x*256 + threadIdx.x;
    if (idx >= 192*512) return;
    int n = idx >> 9, dp = idx & 511;
    const float* W = (n < 64) ? Wq : (n < 128) ? Wk : Wv;
    int h = n & 63, d = dp*2;
    g_Wth[idx] = pack2h(W[d*64 + h], W[(d+1)*64 + h]);
}

// ---------------------------------------------------------------------------
// Kernel 1: QKV via mma.sync pure fp16, UNIFIED 192 cols per CTA (X read
// once).  grid 128.  CTA: 128 rows x 192 cols (Q|K|V).
// smem: Xf16 16KB @0 (single buffer); W double buffer 24KB @16384/@40960.
// X fp32 prefetched one chunk ahead into registers, converted inline.
// ---------------------------------------------------------------------------
extern __shared__ char dsm[];

__global__ __launch_bounds__(256) void qkv_mma(const float* __restrict__ X)
{
    uint32_t sb = smem_u32(dsm);
    const int tid = threadIdx.x, w = tid >> 5, lane = tid & 31;
    const int gid = lane >> 2, tig = lane & 3;
    const int row0 = blockIdx.x * 128;
    const int mrow = w * 16;

    const int aR   = mrow + (lane & 7) + ((lane >> 3) & 1) * 8;
    const uint32_t aOff = (uint32_t)aR * 128;
    const int aSeg = (lane >> 4) ? 16 : 0;
    const uint32_t aX = (uint32_t)((lane & 7) << 4);
    const uint32_t bOff = (uint32_t)((lane & 7) * 128);
    const int bSeg = (lane & 8) ? 16 : 0;
    const uint32_t bX = (uint32_t)((lane & 7) << 4);
    const int ntHi = (lane >> 4) & 1;

    const int xr_r  = tid >> 5;
    const int xr_cp = tid & 31;

    float acc[24][4];
    #pragma unroll
    for (int nt = 0; nt < 24; ++nt)
        #pragma unroll
        for (int j = 0; j < 4; ++j) acc[nt][j] = 0.f;

    #define WSTAGE(buf, kc) do {                                              \
        uint32_t _b = sb + 16384u + (uint32_t)(buf)*24576;                    \
        _Pragma("unroll")                                                     \
        for (int _i = 0; _i < 6; ++_i) {           /* 1536: W 16B units */    \
            int _idx = tid + 256*_i;                                          \
            int _r = _idx >> 3, _c4 = _idx & 7;                               \
            uint32_t _o = swz(_r, _c4*16);                                    \
            cpasync16(_b + _o,                                                \
                      g_Wth + (size_t)_r*512 + (kc)*32 + _c4*4);              \
        }                                                                     \
        CP_COMMIT();                                                          \
    } while (0)

    float2 xr[16];
    #pragma unroll
    for (int i = 0; i < 16; ++i)
        xr[i] = *(const float2*)(X + (size_t)(row0 + xr_r + 8*i)*DD + 2*xr_cp);
    WSTAGE(0, 0);

    for (int kc = 0; kc < 16; ++kc) {
        __syncthreads();                           // A: prior MMA done
        #pragma unroll
        for (int i = 0; i < 16; ++i) {
            uint32_t off = swz(xr_r + 8*i, xr_cp*4);
            *(uint32_t*)(dsm + off) = pack2h(xr[i].x, xr[i].y);
        }
        if (kc + 1 < 16) {
            WSTAGE((kc+1) & 1, kc+1);
            #pragma unroll
            for (int i = 0; i < 16; ++i)
                xr[i] = *(const float2*)(X + (size_t)(row0 + xr_r + 8*i)*DD
                                           + (kc+1)*64 + 2*xr_cp);
            CP_WAIT1();
        } else {
            CP_WAIT0();
        }
        __syncthreads();                           // B: STS + W(kc) visible

        const uint32_t wbase = sb + 16384u + (uint32_t)((kc & 1) * 24576);
        #pragma unroll
        for (int ks = 0; ks < 4; ++ks) {
            uint32_t ah[4];
            ldsm4(ah, sb + aOff + (uint32_t)((ks*32 + aSeg) ^ aX));
            uint32_t kk = bOff + (uint32_t)((ks*32 + bSeg) ^ bX);
            #pragma unroll
            for (int p = 0; p < 12; ++p) {
                uint32_t bh4[4];
                ldsm4(bh4, wbase + (uint32_t)((2*p + ntHi)*1024) + kk);
                mma16816(acc[2*p],   ah, bh4);
                mma16816(acc[2*p+1], ah, bh4+2);
            }
        }
    }
    #undef WSTAGE

    __syncthreads();
    const int r0g = row0 + mrow + gid, r1g = r0g + 8;
    // Q: tiles 0..7, scaled
    #pragma unroll
    for (int nt = 0; nt < 8; ++nt) {
        g_Qh[r0g*32 + nt*4 + tig] = pack2h(acc[nt][0]*QSC, acc[nt][1]*QSC);
        g_Qh[r1g*32 + nt*4 + tig] = pack2h(acc[nt][2]*QSC, acc[nt][3]*QSC);
    }
    // K: tiles 8..15
    #pragma unroll
    for (int nt = 8; nt < 16; ++nt) {
        int c = (nt - 8)*4 + tig;
        g_Kh[r0g*32 + c] = pack2h(acc[nt][0], acc[nt][1]);
        g_Kh[r1g*32 + c] = pack2h(acc[nt][2], acc[nt][3]);
    }
    // V: tiles 16..23, transpose via smem (reuse X area; 32KB)
    float* Vt = (float*)dsm;
    #pragma unroll
    for (int nt = 16; nt < 24; ++nt) {
        int h0 = (nt - 16)*8 + tig*2;
        Vt[h0*128 + mrow + gid]         = acc[nt][0];
        Vt[(h0+1)*128 + mrow + gid]     = acc[nt][1];
        Vt[h0*128 + mrow + gid + 8]     = acc[nt][2];
        Vt[(h0+1)*128 + mrow + gid + 8] = acc[nt][3];
    }
    __syncthreads();
    const int bb = row0 >> 12, sloc = row0 & 4095;
    #pragma unroll
    for (int i = 0; i < 16; ++i) {
        int idx = tid + 256*i;
        int h = idx >> 6, sp = idx & 63;
        size_t o = (size_t)(bb*64 + h)*2048 + (sloc >> 1) + sp;
        g_Vth[o] = pack2h(Vt[h*128 + 2*sp], Vt[h*128 + 2*sp + 1]);
    }
}

// ---------------------------------------------------------------------------
// Kernel 2: causal attention, fp16 hi operands, no-max softmax (f16x2 exp2),
// row-sums via ones-column MMA, 4-way split-K.
// grid (128, 4): qq = 31-(bx>>2) longest-first, s = bx&3.
// TWO k-tiles per pipeline stage; ring-of-3 x 32KB = 96KB.
// ---------------------------------------------------------------------------
__global__ __launch_bounds__(256) void attn_mma()
{
    uint32_t sb = smem_u32(dsm);
    const int tid = threadIdx.x, w = tid >> 5, lane = tid & 31;
    const int gid = lane >> 2, tig = lane & 3;
    const int qq = 31 - ((int)blockIdx.x >> 2);
    const int s  = blockIdx.x & 3;
    const int b  = blockIdx.y;
    const int q0 = qq * 128;
    const int n  = (2*qq + 2 - s + 3) >> 2;        // #k-tiles for this split
    const int npair = (n + 1) >> 1;                // pipeline stages

    const uint32_t bOff = (uint32_t)((lane & 7) * 128);
    const int bSeg = (lane & 8) ? 16 : 0;
    const uint32_t bX = (uint32_t)((lane & 7) << 4);
    const int ntHi = (lane >> 4) & 1;

    const uint32_t* KH = g_Kh + (size_t)(b*SS)*32;
    const uint32_t* VH = g_Vth + (size_t)(b*64)*2048;

    // Q fragments (hi only, registers)
    const int r0g = b*SS + q0 + w*16 + gid, r1g = r0g + 8;
    uint32_t qf[4][4];
    #pragma unroll
    for (int ks = 0; ks < 4; ++ks) {
        qf[ks][0] = g_Qh[r0g*32 + ks*8 + tig];
        qf[ks][1] = g_Qh[r1g*32 + ks*8 + tig];
        qf[ks][2] = g_Qh[r0g*32 + ks*8 + 4 + tig];
        qf[ks][3] = g_Qh[r1g*32 + ks*8 + 4 + tig];
    }

    float oc[8][4];
    #pragma unroll
    for (int nt = 0; nt < 8; ++nt)
        #pragma unroll
        for (int c = 0; c < 4; ++c) oc[nt][c] = 0.f;
    float lsacc[4] = {0.f, 0.f, 0.f, 0.f};         // ones-column row sums
    const uint32_t ones2[2] = {0x3C003C00u, 0x3C003C00u};
    const int qg0 = q0 + w*16 + gid, qg1 = qg0 + 8;

    #define STAGE(buf, u) do {                                                \
        uint32_t _b = sb + (uint32_t)(buf)*32768;                             \
        int _t0 = 2*(u);                                                      \
        int _k0 = (s + 4*_t0) * 64;                                           \
        _Pragma("unroll")                                                     \
        for (int _i = 0; _i < 2; ++_i) {                                      \
            int _idx = tid + 256*_i;                                          \
            int _r = _idx >> 3, _c4 = _idx & 7;                               \
            uint32_t _o = swz(_r, _c4*16);                                    \
            cpasync16(_b + _o,        KH + (size_t)(_k0+_r)*32 + _c4*4);      \
            cpasync16(_b + 8192 + _o, VH + (size_t)_r*2048 + (_k0>>1) + _c4*4);\
        }                                                                     \
        if (_t0 + 1 < n) {                                                    \
            int _k1 = _k0 + 256;                                              \
            _Pragma("unroll")                                                 \
            for (int _i = 0; _i < 2; ++_i) {                                  \
                int _idx = tid + 256*_i;                                      \
                int _r = _idx >> 3, _c4 = _idx & 7;                           \
                uint32_t _o = swz(_r, _c4*16);                                \
                cpasync16(_b + 16384 + _o, KH + (size_t)(_k1+_r)*32 + _c4*4); \
                cpasync16(_b + 24576 + _o,                                    \
                          VH + (size_t)_r*2048 + (_k1>>1) + _c4*4);           \
            }                                                                 \
        }                                                                     \
        CP_COMMIT();                                                          \
    } while (0)

    #define COMPUTE(stoff, k0c) do {                                          \
        float sc[8][4];                                                       \
        _Pragma("unroll")                                                     \
        for (int nt = 0; nt < 8; ++nt)                                        \
            _Pragma("unroll")                                                 \
            for (int c = 0; c < 4; ++c) sc[nt][c] = 0.f;                      \
        _Pragma("unroll")                                                     \
        for (int ks = 0; ks < 4; ++ks) {                                      \
            uint32_t kk = bOff + (uint32_t)((ks*32 + bSeg) ^ bX);             \
            _Pragma("unroll")                                                 \
            for (int p = 0; p < 4; ++p) {                                     \
                uint32_t bh4[4];                                              \
                ldsm4(bh4, (stoff) + (uint32_t)((2*p + ntHi)*1024) + kk);     \
                mma16816(sc[2*p],   qf[ks], bh4);                             \
                mma16816(sc[2*p+1], qf[ks], bh4+2);                           \
            }                                                                 \
        }                                                                     \
        uint32_t ph[16];                                                      \
        if ((k0c) >= q0) {                                                    \
            _Pragma("unroll")                                                 \
            for (int nt = 0; nt < 8; ++nt) {                                  \
                int kg = (k0c) + nt*8 + tig*2;                                \
                float m0 = (kg     <= qg0) ? sc[nt][0] : -3e4f;               \
                float m1 = (kg + 1 <= qg0) ? sc[nt][1] : -3e4f;               \
                float m2 = (kg     <= qg1) ? sc[nt][2] : -3e4f;               \
                float m3 = (kg + 1 <= qg1) ? sc[nt][3] : -3e4f;               \
                ph[nt*2]     = h2ex2(pack2h(m0, m1));                         \
                ph[nt*2 + 1] = h2ex2(pack2h(m2, m3));                         \
            }                                                                 \
        } else {                                                              \
            _Pragma("unroll")                                                 \
            for (int nt = 0; nt < 8; ++nt) {                                  \
                ph[nt*2]     = h2ex2(pack2h(sc[nt][0], sc[nt][1]));           \
                ph[nt*2 + 1] = h2ex2(pack2h(sc[nt][2], sc[nt][3]));           \
            }                                                                 \
        }                                                                     \
        _Pragma("unroll")                                                     \
        for (int kc = 0; kc < 4; ++kc) {                                      \
            uint32_t kk = bOff + (uint32_t)((kc*32 + bSeg) ^ bX);             \
            const uint32_t* ahp = &ph[kc*4];                                  \
            mma16816(lsacc, ahp, ones2);                                      \
            _Pragma("unroll")                                                 \
            for (int p = 0; p < 4; ++p) {                                     \
                uint32_t bh4[4];                                              \
                ldsm4(bh4, (stoff) + 8192 + (uint32_t)((2*p + ntHi)*1024) + kk);\
                mma16816(oc[2*p],   ahp, bh4);                                \
                mma16816(oc[2*p+1], ahp, bh4+2);                              \
            }                                                                 \
        }                                                                     \
    } while (0)

    if (npair > 0) {
        STAGE(0, 0);
        if (npair > 1) STAGE(1, 1);

        int buf = 0;                                // u % 3
        for (int u = 0; u < npair; ++u) {
            if (u + 1 < npair) CP_WAIT1(); else CP_WAIT0();
            __syncthreads();
            if (u + 2 < npair) {
                int nb = buf + 2; if (nb >= 3) nb -= 3;
                STAGE(nb, u + 2);
            }
            const uint32_t st = sb + (uint32_t)(buf * 32768);
            const int t0 = 2*u;
            const int k0a = (s + 4*t0) * 64;
            COMPUTE(st, k0a);
            if (t0 + 1 < n) {
                COMPUTE(st + 16384, k0a + 256);
            }
            if (++buf >= 3) buf = 0;
        }
    }
    #undef STAGE
    #undef COMPUTE

    // write partial O (f16x2) + row sums (col 0 of ones-MMA, tig==0 lanes)
    uint32_t* Og = g_Oh[s];
    const size_t ob0 = (size_t)(b*SS + q0 + w*16 + gid)*32;
    #pragma unroll
    for (int nt = 0; nt < 8; ++nt) {
        Og[ob0 + nt*4 + tig]        = pack2h(oc[nt][0], oc[nt][1]);
        Og[ob0 + 8*32 + nt*4 + tig] = pack2h(oc[nt][2], oc[nt][3]);
    }
    if (tig == 0) {
        g_L[s][b*SS + q0 + w*16 + gid]     = lsacc[0];
        g_L[s][b*SS + q0 + w*16 + gid + 8] = lsacc[2];
    }
}

// ---------------------------------------------------------------------------
// Kernel 3: combine 4 f16x2 split-k partials and normalize.
// Each thread: 2 pairs (LDG.64 x4, STG.128).
// ---------------------------------------------------------------------------
__global__ __launch_bounds__(256) void finalize(float* __restrict__ out)
{
    int idx = blockIdx.x*256 + threadIdx.x;        // over NROW*16 pair-duos
    int row = idx >> 4;
    float l = g_L[0][row] + g_L[1][row] + g_L[2][row] + g_L[3][row];
    float linv = 1.f / l;
    float s0 = 0.f, s1 = 0.f, s2 = 0.f, s3 = 0.f;
    #pragma unroll
    for (int k = 0; k < NSPL; ++k) {
        uint2 v = ((const uint2*)g_Oh[k])[idx];
        __half2 h0 = *reinterpret_cast<__half2*>(&v.x);
        __half2 h1 = *reinterpret_cast<__half2*>(&v.y);
        s0 += __low2float(h0);  s1 += __high2float(h0);
        s2 += __low2float(h1);  s3 += __high2float(h1);
    }
    ((float4*)out)[idx] = make_float4(s0*linv, s1*linv, s2*linv, s3*linv);
}

// ---------------------------------------------------------------------------
extern "C" void kernel_launch(void* const* d_in, const int* in_sizes, int n_in,
                              void* d_out, int out_size)
{
    const float* X  = (const float*)d_in[0];
    const float* Wq = (const float*)d_in[1];
    const float* Wk = (const float*)d_in[2];
    const float* Wv = (const float*)d_in[3];
    float* out = (float*)d_out;

    prep_w<<<384, 256>>>(Wq, Wk, Wv);

    const int qkv_smem = 65536;
    cudaFuncSetAttribute(qkv_mma,
                         cudaFuncAttributeMaxDynamicSharedMemorySize, qkv_smem);
    qkv_mma<<<128, 256, qkv_smem>>>(X);

    const int attn_smem = 98304;
    cudaFuncSetAttribute(attn_mma,
                         cudaFuncAttributeMaxDynamicSharedMemorySize, attn_smem);
    attn_mma<<<dim3(128, BB), 256, attn_smem>>>();

    finalize<<<(NROW*16)/256, 256>>>(out);
}

// round 17
// speedup vs baseline: 2.1882x; 1.0004x over previous
#include <cuda_runtime.h>
#include <cuda_fp16.h>
#include <cstdint>
#include <math.h>

#define BB 4
#define SS 4096
#define DD 1024
#define HH 64
#define NROW (BB*SS)
#define NSPL 4

// Q scale: 1/8 softmax scale * log2(e) for ex2-based exp
#define QSC 0.18033688011112042f

// ---------------- scratch (__device__ globals; allocation-free rule) -------
__device__ uint32_t g_Qh[NROW*32];                      // [row][d-pair] f16x2
__device__ uint32_t g_Kh[NROW*32];                      // [row][d-pair] (hi only)
__device__ uint32_t g_Vth[BB*64*2048];                  // [b][h][seq-pair] (hi only)
__device__ uint32_t g_Wth[192*512];                     // [n(=3*64)][d-pair] (hi only)
__device__ uint32_t g_Oh[NSPL][NROW*32];                // split-k partial O, f16x2
__device__ float    g_L[NSPL][NROW];                    // split-k partial rowsum

// ---------------- helpers --------------------------------------------------
__device__ __forceinline__ uint32_t smem_u32(const void* p){
    uint32_t a;
    asm("{ .reg .u64 t; cvta.to.shared.u64 t, %1; cvt.u32.u64 %0, t; }"
        : "=r"(a) : "l"(p));
    return a;
}
__device__ __forceinline__ void mma16816(float* d, const uint32_t* a,
                                         const uint32_t* b){
    asm volatile(
        "mma.sync.aligned.m16n8k16.row.col.f32.f16.f16.f32 "
        "{%0,%1,%2,%3}, {%4,%5,%6,%7}, {%8,%9}, {%0,%1,%2,%3};"
        : "+f"(d[0]), "+f"(d[1]), "+f"(d[2]), "+f"(d[3])
        : "r"(a[0]), "r"(a[1]), "r"(a[2]), "r"(a[3]), "r"(b[0]), "r"(b[1]));
}
__device__ __forceinline__ void ldsm4(uint32_t* r, uint32_t addr){
    asm volatile("ldmatrix.sync.aligned.m8n8.x4.shared.b16 {%0,%1,%2,%3}, [%4];"
        : "=r"(r[0]), "=r"(r[1]), "=r"(r[2]), "=r"(r[3]) : "r"(addr));
}
__device__ __forceinline__ void cpasync16(uint32_t dst, const void* src){
    asm volatile("cp.async.cg.shared.global [%0], [%1], 16;"
                 :: "r"(dst), "l"(src));
}
#define CP_COMMIT() asm volatile("cp.async.commit_group;" ::: "memory")
#define CP_WAIT1()  asm volatile("cp.async.wait_group 1;" ::: "memory")
#define CP_WAIT0()  asm volatile("cp.async.wait_group 0;" ::: "memory")

// fp16x2 pack: f0 -> low half, f1 -> high half
__device__ __forceinline__ uint32_t pack2h(float f0, float f1){
    uint32_t r;
    asm("cvt.rn.f16x2.f32 %0, %1, %2;" : "=r"(r) : "f"(f1), "f"(f0));
    return r;
}
// packed fp16x2 exp2
__device__ __forceinline__ uint32_t h2ex2(uint32_t x){
    uint32_t r;
    asm("ex2.approx.f16x2 %0, %1;" : "=r"(r) : "r"(x));
    return r;
}
// swizzled byte offset inside a [row][128B] tile (conflict-free ldmatrix)
__device__ __forceinline__ uint32_t swz(int r, int bytecol){
    return (uint32_t)(r*128 + (bytecol ^ ((r & 7) << 4)));
}

// ---------------------------------------------------------------------------
// Kernel 0: W transpose -> fp16 hi.
// ---------------------------------------------------------------------------
__global__ __launch_bounds__(256) void prep_w(
    const float* __restrict__ Wq, const float* __restrict__ Wk,
    const float* __restrict__ Wv)
{
    int idx = blockIdx.x*256 + threadIdx.x;
    if (idx >= 192*512) return;
    int n = idx >> 9, dp = idx & 511;
    const float* W = (n < 64) ? Wq : (n < 128) ? Wk : Wv;
    int h = n & 63, d = dp*2;
    g_Wth[idx] = pack2h(W[d*64 + h], W[(d+1)*64 + h]);
}

// ---------------------------------------------------------------------------
// Kernel 1: QKV via mma.sync pure fp16.  256 CTAs x 64 rows x 192 cols.
// 8 warps = 4 row-groups (16 rows) x 2 col-halves (96 cols = 12 n-tiles).
// smem: Xf16 8KB @0 (single buffer); W double buffer 24KB @8192/@32768
// -> 56KB total, 2 CTAs/SM.  X fp32 prefetched one chunk ahead.
// ---------------------------------------------------------------------------
extern __shared__ char dsm[];

__global__ __launch_bounds__(256) void qkv_mma(const float* __restrict__ X)
{
    uint32_t sb = smem_u32(dsm);
    const int tid = threadIdx.x, w = tid >> 5, lane = tid & 31;
    const int gid = lane >> 2, tig = lane & 3;
    const int row0 = blockIdx.x * 64;
    const int mrow = (w >> 1) * 16;                // row group
    const int ch   = w & 1;                        // column half (96 cols)

    const int aR   = mrow + (lane & 7) + ((lane >> 3) & 1) * 8;
    const uint32_t aOff = (uint32_t)aR * 128;
    const int aSeg = (lane >> 4) ? 16 : 0;
    const uint32_t aX = (uint32_t)((lane & 7) << 4);
    const uint32_t bOff = (uint32_t)((lane & 7) * 128);
    const int bSeg = (lane & 8) ? 16 : 0;
    const uint32_t bX = (uint32_t)((lane & 7) << 4);
    const int ntHi = (lane >> 4) & 1;

    const int xr_r  = tid >> 5;                    // rows 0..7 (+8 per i)
    const int xr_cp = tid & 31;

    float acc[12][4];
    #pragma unroll
    for (int nt = 0; nt < 12; ++nt)
        #pragma unroll
        for (int j = 0; j < 4; ++j) acc[nt][j] = 0.f;

    #define WSTAGE(buf, kc) do {                                              \
        uint32_t _b = sb + 8192u + (uint32_t)(buf)*24576;                     \
        _Pragma("unroll")                                                     \
        for (int _i = 0; _i < 6; ++_i) {           /* 1536: W 16B units */    \
            int _idx = tid + 256*_i;                                          \
            int _r = _idx >> 3, _c4 = _idx & 7;                               \
            uint32_t _o = swz(_r, _c4*16);                                    \
            cpasync16(_b + _o,                                                \
                      g_Wth + (size_t)_r*512 + (kc)*32 + _c4*4);              \
        }                                                                     \
        CP_COMMIT();                                                          \
    } while (0)

    float2 xr[8];
    #pragma unroll
    for (int i = 0; i < 8; ++i)
        xr[i] = *(const float2*)(X + (size_t)(row0 + xr_r + 8*i)*DD + 2*xr_cp);
    WSTAGE(0, 0);

    for (int kc = 0; kc < 16; ++kc) {
        __syncthreads();                           // A: prior MMA done
        #pragma unroll
        for (int i = 0; i < 8; ++i) {
            uint32_t off = swz(xr_r + 8*i, xr_cp*4);
            *(uint32_t*)(dsm + off) = pack2h(xr[i].x, xr[i].y);
        }
        if (kc + 1 < 16) {
            WSTAGE((kc+1) & 1, kc+1);
            #pragma unroll
            for (int i = 0; i < 8; ++i)
                xr[i] = *(const float2*)(X + (size_t)(row0 + xr_r + 8*i)*DD
                                           + (kc+1)*64 + 2*xr_cp);
            CP_WAIT1();
        } else {
            CP_WAIT0();
        }
        __syncthreads();                           // B: STS + W(kc) visible

        const uint32_t wbase = sb + 8192u + (uint32_t)((kc & 1) * 24576);
        #pragma unroll
        for (int ks = 0; ks < 4; ++ks) {
            uint32_t ah[4];
            ldsm4(ah, sb + aOff + (uint32_t)((ks*32 + aSeg) ^ aX));
            uint32_t kk = bOff + (uint32_t)((ks*32 + bSeg) ^ bX);
            #pragma unroll
            for (int p = 0; p < 6; ++p) {
                uint32_t bh4[4];
                uint32_t ta = wbase + (uint32_t)((ch*12 + 2*p + ntHi)*1024) + kk;
                ldsm4(bh4, ta);
                mma16816(acc[2*p],   ah, bh4);
                mma16816(acc[2*p+1], ah, bh4+2);
            }
        }
    }
    #undef WSTAGE

    __syncthreads();
    const int r0g = row0 + mrow + gid, r1g = r0g + 8;
    float* Vt = (float*)dsm;                       // [h][64 seq], 16KB
    #pragma unroll
    for (int nt = 0; nt < 12; ++nt) {
        int gnt = ch*12 + nt;                      // global 8-col tile
        if (gnt < 8) {
            // Q: scaled
            g_Qh[r0g*32 + gnt*4 + tig] = pack2h(acc[nt][0]*QSC, acc[nt][1]*QSC);
            g_Qh[r1g*32 + gnt*4 + tig] = pack2h(acc[nt][2]*QSC, acc[nt][3]*QSC);
        } else if (gnt < 16) {
            int c = (gnt - 8)*4 + tig;
            g_Kh[r0g*32 + c] = pack2h(acc[nt][0], acc[nt][1]);
            g_Kh[r1g*32 + c] = pack2h(acc[nt][2], acc[nt][3]);
        } else {
            int h0 = (gnt - 16)*8 + tig*2;
            Vt[h0*64 + mrow + gid]         = acc[nt][0];
            Vt[(h0+1)*64 + mrow + gid]     = acc[nt][1];
            Vt[h0*64 + mrow + gid + 8]     = acc[nt][2];
            Vt[(h0+1)*64 + mrow + gid + 8] = acc[nt][3];
        }
    }
    __syncthreads();
    const int bb = row0 >> 12, sloc = row0 & 4095;
    #pragma unroll
    for (int i = 0; i < 8; ++i) {
        int idx = tid + 256*i;                     // 2048: h(64) x sp(32)
        int h = idx >> 5, sp = idx & 31;
        size_t o = (size_t)(bb*64 + h)*2048 + (sloc >> 1) + sp;
        g_Vth[o] = pack2h(Vt[h*64 + 2*sp], Vt[h*64 + 2*sp + 1]);
    }
}

// ---------------------------------------------------------------------------
// Kernel 2: causal attention, fp16 hi operands, no-max softmax (f16x2 exp2),
// row-sums via ones-column MMA, 4-way split-K.
// grid (128, 4): qq = 31-(bx>>2) longest-first, s = bx&3.
// TWO k-tiles per pipeline stage; ring-of-3 x 32KB = 96KB.
// ---------------------------------------------------------------------------
__global__ __launch_bounds__(256) void attn_mma()
{
    uint32_t sb = smem_u32(dsm);
    const int tid = threadIdx.x, w = tid >> 5, lane = tid & 31;
    const int gid = lane >> 2, tig = lane & 3;
    const int qq = 31 - ((int)blockIdx.x >> 2);
    const int s  = blockIdx.x & 3;
    const int b  = blockIdx.y;
    const int q0 = qq * 128;
    const int n  = (2*qq + 2 - s + 3) >> 2;        // #k-tiles for this split
    const int npair = (n + 1) >> 1;                // pipeline stages

    const uint32_t bOff = (uint32_t)((lane & 7) * 128);
    const int bSeg = (lane & 8) ? 16 : 0;
    const uint32_t bX = (uint32_t)((lane & 7) << 4);
    const int ntHi = (lane >> 4) & 1;

    const uint32_t* KH = g_Kh + (size_t)(b*SS)*32;
    const uint32_t* VH = g_Vth + (size_t)(b*64)*2048;

    // Q fragments (hi only, registers)
    const int r0g = b*SS + q0 + w*16 + gid, r1g = r0g + 8;
    uint32_t qf[4][4];
    #pragma unroll
    for (int ks = 0; ks < 4; ++ks) {
        qf[ks][0] = g_Qh[r0g*32 + ks*8 + tig];
        qf[ks][1] = g_Qh[r1g*32 + ks*8 + tig];
        qf[ks][2] = g_Qh[r0g*32 + ks*8 + 4 + tig];
        qf[ks][3] = g_Qh[r1g*32 + ks*8 + 4 + tig];
    }

    float oc[8][4];
    #pragma unroll
    for (int nt = 0; nt < 8; ++nt)
        #pragma unroll
        for (int c = 0; c < 4; ++c) oc[nt][c] = 0.f;
    float lsacc[4] = {0.f, 0.f, 0.f, 0.f};         // ones-column row sums
    const uint32_t ones2[2] = {0x3C003C00u, 0x3C003C00u};
    const int qg0 = q0 + w*16 + gid, qg1 = qg0 + 8;

    #define STAGE(buf, u) do {                                                \
        uint32_t _b = sb + (uint32_t)(buf)*32768;                             \
        int _t0 = 2*(u);                                                      \
        int _k0 = (s + 4*_t0) * 64;                                           \
        _Pragma("unroll")                                                     \
        for (int _i = 0; _i < 2; ++_i) {                                      \
            int _idx = tid + 256*_i;                                          \
            int _r = _idx >> 3, _c4 = _idx & 7;                               \
            uint32_t _o = swz(_r, _c4*16);                                    \
            cpasync16(_b + _o,        KH + (size_t)(_k0+_r)*32 + _c4*4);      \
            cpasync16(_b + 8192 + _o, VH + (size_t)_r*2048 + (_k0>>1) + _c4*4);\
        }                                                                     \
        if (_t0 + 1 < n) {                                                    \
            int _k1 = _k0 + 256;                                              \
            _Pragma("unroll")                                                 \
            for (int _i = 0; _i < 2; ++_i) {                                  \
                int _idx = tid + 256*_i;                                      \
                int _r = _idx >> 3, _c4 = _idx & 7;                           \
                uint32_t _o = swz(_r, _c4*16);                                \
                cpasync16(_b + 16384 + _o, KH + (size_t)(_k1+_r)*32 + _c4*4); \
                cpasync16(_b + 24576 + _o,                                    \
                          VH + (size_t)_r*2048 + (_k1>>1) + _c4*4);           \
            }                                                                 \
        }                                                                     \
        CP_COMMIT();                                                          \
    } while (0)

    #define COMPUTE(stoff, k0c) do {                                          \
        float sc[8][4];                                                       \
        _Pragma("unroll")                                                     \
        for (int nt = 0; nt < 8; ++nt)                                        \
            _Pragma("unroll")                                                 \
            for (int c = 0; c < 4; ++c) sc[nt][c] = 0.f;                      \
        _Pragma("unroll")                                                     \
        for (int ks = 0; ks < 4; ++ks) {                                      \
            uint32_t kk = bOff + (uint32_t)((ks*32 + bSeg) ^ bX);             \
            _Pragma("unroll")                                                 \
            for (int p = 0; p < 4; ++p) {                                     \
                uint32_t bh4[4];                                              \
                ldsm4(bh4, (stoff) + (uint32_t)((2*p + ntHi)*1024) + kk);     \
                mma16816(sc[2*p],   qf[ks], bh4);                             \
                mma16816(sc[2*p+1], qf[ks], bh4+2);                           \
            }                                                                 \
        }                                                                     \
        uint32_t ph[16];                                                      \
        if ((k0c) >= q0) {                                                    \
            _Pragma("unroll")                                                 \
            for (int nt = 0; nt < 8; ++nt) {                                  \
                int kg = (k0c) + nt*8 + tig*2;                                \
                float m0 = (kg     <= qg0) ? sc[nt][0] : -3e4f;               \
                float m1 = (kg + 1 <= qg0) ? sc[nt][1] : -3e4f;               \
                float m2 = (kg     <= qg1) ? sc[nt][2] : -3e4f;               \
                float m3 = (kg + 1 <= qg1) ? sc[nt][3] : -3e4f;               \
                ph[nt*2]     = h2ex2(pack2h(m0, m1));                         \
                ph[nt*2 + 1] = h2ex2(pack2h(m2, m3));                         \
            }                                                                 \
        } else {                                                              \
            _Pragma("unroll")                                                 \
            for (int nt = 0; nt < 8; ++nt) {                                  \
                ph[nt*2]     = h2ex2(pack2h(sc[nt][0], sc[nt][1]));           \
                ph[nt*2 + 1] = h2ex2(pack2h(sc[nt][2], sc[nt][3]));           \
            }                                                                 \
        }                                                                     \
        _Pragma("unroll")                                                     \
        for (int kc = 0; kc < 4; ++kc) {                                      \
            uint32_t kk = bOff + (uint32_t)((kc*32 + bSeg) ^ bX);             \
            const uint32_t* ahp = &ph[kc*4];                                  \
            mma16816(lsacc, ahp, ones2);                                      \
            _Pragma("unroll")                                                 \
            for (int p = 0; p < 4; ++p) {                                     \
                uint32_t bh4[4];                                              \
                ldsm4(bh4, (stoff) + 8192 + (uint32_t)((2*p + ntHi)*1024) + kk);\
                mma16816(oc[2*p],   ahp, bh4);                                \
                mma16816(oc[2*p+1], ahp, bh4+2);                              \
            }                                                                 \
        }                                                                     \
    } while (0)

    if (npair > 0) {
        STAGE(0, 0);
        if (npair > 1) STAGE(1, 1);

        int buf = 0;                                // u % 3
        for (int u = 0; u < npair; ++u) {
            if (u + 1 < npair) CP_WAIT1(); else CP_WAIT0();
            __syncthreads();
            if (u + 2 < npair) {
                int nb = buf + 2; if (nb >= 3) nb -= 3;
                STAGE(nb, u + 2);
            }
            const uint32_t st = sb + (uint32_t)(buf * 32768);
            const int t0 = 2*u;
            const int k0a = (s + 4*t0) * 64;
            COMPUTE(st, k0a);
            if (t0 + 1 < n) {
                COMPUTE(st + 16384, k0a + 256);
            }
            if (++buf >= 3) buf = 0;
        }
    }
    #undef STAGE
    #undef COMPUTE

    // write partial O (f16x2) + row sums (col 0 of ones-MMA, tig==0 lanes)
    uint32_t* Og = g_Oh[s];
    const size_t ob0 = (size_t)(b*SS + q0 + w*16 + gid)*32;
    #pragma unroll
    for (int nt = 0; nt < 8; ++nt) {
        Og[ob0 + nt*4 + tig]        = pack2h(oc[nt][0], oc[nt][1]);
        Og[ob0 + 8*32 + nt*4 + tig] = pack2h(oc[nt][2], oc[nt][3]);
    }
    if (tig == 0) {
        g_L[s][b*SS + q0 + w*16 + gid]     = lsacc[0];
        g_L[s][b*SS + q0 + w*16 + gid + 8] = lsacc[2];
    }
}

// ---------------------------------------------------------------------------
// Kernel 3: combine 4 f16x2 split-k partials and normalize.
// Each thread: 4 pairs (uint4 LDG.128 x4, STG.128 x2).
// ---------------------------------------------------------------------------
__global__ __launch_bounds__(256) void finalize(float* __restrict__ out)
{
    int idx = blockIdx.x*256 + threadIdx.x;        // over NROW*8 pair-quads
    int row = idx >> 3;
    float l = g_L[0][row] + g_L[1][row] + g_L[2][row] + g_L[3][row];
    float linv = 1.f / l;
    float s[8] = {0.f,0.f,0.f,0.f,0.f,0.f,0.f,0.f};
    #pragma unroll
    for (int k = 0; k < NSPL; ++k) {
        uint4 v = ((const uint4*)g_Oh[k])[idx];
        uint32_t vv[4] = {v.x, v.y, v.z, v.w};
        #pragma unroll
        for (int j = 0; j < 4; ++j) {
            __half2 h = *reinterpret_cast<__half2*>(&vv[j]);
            s[2*j]   += __low2float(h);
            s[2*j+1] += __high2float(h);
        }
    }
    float4* o4 = (float4*)out;
    o4[idx*2]     = make_float4(s[0]*linv, s[1]*linv, s[2]*linv, s[3]*linv);
    o4[idx*2 + 1] = make_float4(s[4]*linv, s[5]*linv, s[6]*linv, s[7]*linv);
}

// ---------------------------------------------------------------------------
extern "C" void kernel_launch(void* const* d_in, const int* in_sizes, int n_in,
                              void* d_out, int out_size)
{
    const float* X  = (const float*)d_in[0];
    const float* Wq = (const float*)d_in[1];
    const float* Wk = (const float*)d_in[2];
    const float* Wv = (const float*)d_in[3];
    float* out = (float*)d_out;

    prep_w<<<384, 256>>>(Wq, Wk, Wv);

    const int qkv_smem = 57344;
    cudaFuncSetAttribute(qkv_mma,
                         cudaFuncAttributeMaxDynamicSharedMemorySize, qkv_smem);
    qkv_mma<<<256, 256, qkv_smem>>>(X);

    const int attn_smem = 98304;
    cudaFuncSetAttribute(attn_mma,
                         cudaFuncAttributeMaxDynamicSharedMemorySize, attn_smem);
    attn_mma<<<dim3(128, BB), 256, attn_smem>>>();

    finalize<<<(NROW*8)/256, 256>>>(out);
}